// round 5
// baseline (speedup 1.0000x reference)
#include <cuda_runtime.h>
#include <cuda_fp16.h>
#include <math.h>
#include <stdint.h>

#define B_   128
#define T_   256
#define D_   512
#define H_   1024
#define O_   1024
#define G4H  4096
#define NCTA 128
#define HTP  136   // padded batch pitch for transposed h

// ---------------- scratch (static device globals; no allocations) ----------
__device__ float g_xproj[(size_t)B_ * T_ * G4H];   // [B,T,4,H]
__device__ float g_h[B_ * H_];
__device__ float g_c[B_ * H_];
__device__ float g_logits[B_ * O_];
__device__ unsigned g_bar;

__device__ __align__(16) __half g_x16[(size_t)B_ * T_ * D_];
__device__ __align__(16) __half g_Wx16[G4H * D_];
__device__ __align__(16) __half g_Wh16[G4H * H_];
__device__ __align__(16) __half g_h16T[2 * H_ * HTP];   // ping-pong h, [k][b] padded

// ---------------------------------------------------------------------------
// helpers
// ---------------------------------------------------------------------------
__device__ __forceinline__ uint32_t smem_u32(const void* p) {
    return (uint32_t)__cvta_generic_to_shared(p);
}

__device__ __forceinline__ void ldsm4(uint32_t& r0, uint32_t& r1, uint32_t& r2,
                                      uint32_t& r3, uint32_t a) {
    asm volatile("ldmatrix.sync.aligned.m8n8.x4.shared.b16 {%0,%1,%2,%3}, [%4];"
                 : "=r"(r0), "=r"(r1), "=r"(r2), "=r"(r3) : "r"(a));
}

__device__ __forceinline__ void ldsm4t(uint32_t& r0, uint32_t& r1, uint32_t& r2,
                                       uint32_t& r3, uint32_t a) {
    asm volatile("ldmatrix.sync.aligned.m8n8.x4.trans.shared.b16 {%0,%1,%2,%3}, [%4];"
                 : "=r"(r0), "=r"(r1), "=r"(r2), "=r"(r3) : "r"(a));
}

__device__ __forceinline__ void mma_f16(float* c, const uint32_t* a,
                                        uint32_t b0, uint32_t b1) {
    asm volatile(
        "mma.sync.aligned.m16n8k16.row.col.f32.f16.f16.f32 "
        "{%0,%1,%2,%3}, {%4,%5,%6,%7}, {%8,%9}, {%0,%1,%2,%3};"
        : "+f"(c[0]), "+f"(c[1]), "+f"(c[2]), "+f"(c[3])
        : "r"(a[0]), "r"(a[1]), "r"(a[2]), "r"(a[3]), "r"(b0), "r"(b1));
}

__device__ __forceinline__ void cp_async16(uint32_t dst, const void* src) {
    asm volatile("cp.async.cg.shared.global [%0], [%1], 16;" :: "r"(dst), "l"(src));
}
__device__ __forceinline__ void cp_async8(uint32_t dst, const void* src) {
    asm volatile("cp.async.ca.shared.global [%0], [%1], 8;" :: "r"(dst), "l"(src));
}
__device__ __forceinline__ void cp_commit() {
    asm volatile("cp.async.commit_group;");
}
template <int N> __device__ __forceinline__ void cp_wait() {
    asm volatile("cp.async.wait_group %0;" :: "n"(N));
}

__device__ __forceinline__ void mbar_init(uint32_t mbar, uint32_t cnt) {
    asm volatile("mbarrier.init.shared::cta.b64 [%0], %1;" :: "r"(mbar), "r"(cnt));
}
__device__ __forceinline__ void mbar_expect_tx(uint32_t mbar, uint32_t bytes) {
    asm volatile("mbarrier.arrive.expect_tx.shared::cta.b64 _, [%0], %1;"
                 :: "r"(mbar), "r"(bytes));
}
__device__ __forceinline__ void bulk_ldg(uint32_t dst, const void* src,
                                         uint32_t bytes, uint32_t mbar) {
    asm volatile("cp.async.bulk.shared::cta.global.mbarrier::complete_tx::bytes "
                 "[%0], [%1], %2, [%3];"
                 :: "r"(dst), "l"(src), "r"(bytes), "r"(mbar) : "memory");
}
__device__ __forceinline__ void mbar_wait(uint32_t mbar, uint32_t phase) {
    asm volatile(
        "{\n\t.reg .pred p;\n\t"
        "WAIT_%=:\n\t"
        "mbarrier.try_wait.parity.acquire.cta.shared::cta.b64 p, [%0], %1;\n\t"
        "@!p bra WAIT_%=;\n\t}"
        :: "r"(mbar), "r"(phase) : "memory");
}

__device__ __forceinline__ float sigmoidf_(float x) {
    return 1.f / (1.f + __expf(-x));
}

// ---------------------------------------------------------------------------
// conversion kernels
// ---------------------------------------------------------------------------
__global__ void cvt16_kernel(const float* __restrict__ src,
                             __half* __restrict__ dst, int n)
{
    int i = blockIdx.x * blockDim.x + threadIdx.x;
    if (i < n) dst[i] = __float2half(src[i]);
}

__global__ void init_kernel()
{
    int i = blockIdx.x * blockDim.x + threadIdx.x;
    if (i < B_ * H_) g_c[i] = 0.f;
    if (i < 2 * H_ * HTP) g_h16T[i] = __float2half(0.f);
    if (i == 0) g_bar = 0;
}

// ---------------------------------------------------------------------------
// xproj GEMM: xproj[m,n] = x16[m,:] @ Wx16[n,:]^T + bias[n]
// M=32768, N=4096, K=512. CTA tile M128 N64 K32, 128 threads = 4 warps,
// warp tile m32 n64.
// ---------------------------------------------------------------------------
__global__ __launch_bounds__(128)
void xproj_kernel(const float* __restrict__ bias)
{
    __shared__ __align__(16) __half As[128 * 40];
    __shared__ __align__(16) __half Bs[64 * 40];

    const int tid  = threadIdx.x;
    const int lane = tid & 31;
    const int w    = tid >> 5;
    const int m_off = blockIdx.y * 128;
    const int n0    = blockIdx.x * 64;

    float acc[2][8][4];
    #pragma unroll
    for (int mi = 0; mi < 2; mi++)
        #pragma unroll
        for (int ni = 0; ni < 8; ni++)
            #pragma unroll
            for (int r = 0; r < 4; r++) acc[mi][ni][r] = 0.f;

    for (int k0 = 0; k0 < D_; k0 += 32) {
        #pragma unroll
        for (int ii = 0; ii < 4; ii++) {
            int i = tid + ii * 128;
            int row = i >> 2, q = i & 3;
            *(((uint4*)(As + row * 40)) + q) =
                *((const uint4*)(g_x16 + (size_t)(m_off + row) * D_ + k0) + q);
        }
        #pragma unroll
        for (int ii = 0; ii < 2; ii++) {
            int i = tid + ii * 128;
            int rr = i >> 2, q = i & 3;
            *(((uint4*)(Bs + rr * 40)) + q) =
                *((const uint4*)(g_Wx16 + (size_t)(n0 + rr) * D_ + k0) + q);
        }
        __syncthreads();

        #pragma unroll
        for (int kk = 0; kk < 32; kk += 16) {
            uint32_t a[2][4], b[8][2];
            int arow = lane & 15;
            int acol = kk + ((lane >> 4) << 3);
            #pragma unroll
            for (int mi = 0; mi < 2; mi++) {
                uint32_t ad = smem_u32(As + (w * 32 + mi * 16 + arow) * 40 + acol);
                ldsm4(a[mi][0], a[mi][1], a[mi][2], a[mi][3], ad);
            }
            int brl = ((lane >> 4) << 3) + (lane & 7);
            int bcol = kk + (((lane >> 3) & 1) << 3);
            #pragma unroll
            for (int g = 0; g < 4; g++) {
                uint32_t bd = smem_u32(Bs + (g * 16 + brl) * 40 + bcol);
                ldsm4(b[g * 2][0], b[g * 2][1], b[g * 2 + 1][0], b[g * 2 + 1][1], bd);
            }
            #pragma unroll
            for (int mi = 0; mi < 2; mi++)
                #pragma unroll
                for (int ni = 0; ni < 8; ni++)
                    mma_f16(acc[mi][ni], a[mi], b[ni][0], b[ni][1]);
        }
        __syncthreads();
    }

    #pragma unroll
    for (int mi = 0; mi < 2; mi++) {
        #pragma unroll
        for (int ni = 0; ni < 8; ni++) {
            int grow = m_off + w * 32 + mi * 16 + (lane >> 2);
            int gcol = n0 + ni * 8 + ((lane & 3) << 1);
            float b0 = bias[gcol], b1 = bias[gcol + 1];
            float* p0 = g_xproj + (size_t)grow * G4H + gcol;
            p0[0] = acc[mi][ni][0] + b0;
            p0[1] = acc[mi][ni][1] + b1;
            float* p1 = g_xproj + (size_t)(grow + 8) * G4H + gcol;
            p1[0] = acc[mi][ni][2] + b0;
            p1[1] = acc[mi][ni][3] + b1;
        }
    }
}

// ---------------------------------------------------------------------------
// Persistent LSTM recurrence.
// 128 CTAs x 128 threads (4 warps, warp tile m32 n32). CTA owns 8 h-cols x
// 4 gates (32 gate-major Wh rows resident in SMEM).
// h kept TRANSPOSED+padded in gmem: h16T[k=1024][b=136]. Each K=64 chunk is
// one contiguous 17408B cp.async.bulk into a double-buffered smem tile
// (272B rows -> conflict-free ldmatrix.trans). mbarrier completion.
// ---------------------------------------------------------------------------
#define MBAR_OFF  0
#define WH_OFF    128
#define WH_SZ     (32 * 2064)               // 66048
#define AS_OFF    (WH_OFF + WH_SZ)          // 66176
#define AS_BUF_SZ (64 * 272)                // 17408 per buffer
#define XP_OFF    (AS_OFF + 2 * AS_BUF_SZ)  // 100992
#define XP_SZ     (128 * 34 * 4)            // 17408 per buffer
#define SMEM_LSTM (XP_OFF + 2 * XP_SZ)      // 135808

__device__ __forceinline__ void prefetch_xp(uint32_t sbase, int t, int buf,
                                            int col0)
{
    const int lane = threadIdx.x & 31;
    const int w    = threadIdx.x >> 5;
    int q2 = (lane & 3) * 2;
    #pragma unroll
    for (int mi = 0; mi < 2; mi++)
        #pragma unroll
        for (int ro = 0; ro < 2; ro++) {
            int b = w * 32 + mi * 16 + ro * 8 + (lane >> 2);
            #pragma unroll
            for (int g = 0; g < 4; g++) {
                const float* src = g_xproj +
                    (((size_t)b * T_ + t) * 4 + g) * H_ + col0 + q2;
                cp_async8(sbase + XP_OFF + buf * XP_SZ + (b * 34 + g * 8 + q2) * 4,
                          src);
            }
        }
}

__global__ __launch_bounds__(128, 1)
void lstm_persistent_kernel()
{
    extern __shared__ char sm[];
    const int tid  = threadIdx.x;
    const int lane = tid & 31;
    const int w    = tid >> 5;
    const int col0 = blockIdx.x * 8;
    const uint32_t sbase = smem_u32(sm);

    if (tid == 0) {
        mbar_init(sbase + MBAR_OFF, 1);
        mbar_init(sbase + MBAR_OFF + 8, 1);
    }
    __syncthreads();

    // ---- resident Wh load (fp16) + step-0 xproj slice ----
    for (int i = tid; i < 4096; i += 128) {
        int r = i >> 7;
        int c = i & 127;
        int ng = (r >> 3) * H_ + col0 + (r & 7);
        cp_async16(sbase + WH_OFF + r * 2064 + c * 16,
                   g_Wh16 + (size_t)ng * H_ + c * 8);
    }
    prefetch_xp(sbase, 0, 0, col0);
    cp_commit();
    cp_wait<0>();
    __syncthreads();

    uint32_t ph[2] = {0, 0};

    for (int t = 0; t < T_; ++t) {
        const __half* hin = g_h16T + (size_t)(t & 1) * (H_ * HTP);

        // issue chunk 0
        if (tid == 0) {
            mbar_expect_tx(sbase + MBAR_OFF, AS_BUF_SZ);
            bulk_ldg(sbase + AS_OFF, hin, AS_BUF_SZ, sbase + MBAR_OFF);
        }

        float acc[2][4][4];
        #pragma unroll
        for (int mi = 0; mi < 2; mi++)
            #pragma unroll
            for (int ni = 0; ni < 4; ni++)
                #pragma unroll
                for (int r = 0; r < 4; r++) acc[mi][ni][r] = 0.f;

        for (int ch = 0; ch < 16; ++ch) {
            const int buf = ch & 1;
            mbar_wait(sbase + MBAR_OFF + buf * 8, ph[buf]);
            ph[buf] ^= 1;
            __syncthreads();   // all warps done with this buffer's previous use

            if (ch < 15 && tid == 0) {
                const int nb = (ch + 1) & 1;
                mbar_expect_tx(sbase + MBAR_OFF + nb * 8, AS_BUF_SZ);
                bulk_ldg(sbase + AS_OFF + nb * AS_BUF_SZ,
                         hin + (size_t)(ch + 1) * 64 * HTP,
                         AS_BUF_SZ, sbase + MBAR_OFF + nb * 8);
            }

            const uint32_t Abuf = sbase + AS_OFF + buf * AS_BUF_SZ;
            #pragma unroll
            for (int kk = 0; kk < 64; kk += 16) {
                uint32_t a[2][4];
                int krow = kk + ((lane >> 4) << 3) + (lane & 7);
                #pragma unroll
                for (int mi = 0; mi < 2; mi++) {
                    int mcol = w * 32 + mi * 16 + (((lane >> 3) & 1) << 3);
                    ldsm4t(a[mi][0], a[mi][1], a[mi][2], a[mi][3],
                           Abuf + krow * 272 + mcol * 2);
                }
                uint32_t b[4][2];
                #pragma unroll
                for (int nh = 0; nh < 2; nh++) {
                    int row = nh * 16 + ((lane >> 4) << 3) + (lane & 7);
                    int cb  = (ch * 64 + kk + (((lane >> 3) & 1) << 3)) * 2;
                    ldsm4(b[nh * 2][0], b[nh * 2][1],
                          b[nh * 2 + 1][0], b[nh * 2 + 1][1],
                          sbase + WH_OFF + row * 2064 + cb);
                }
                #pragma unroll
                for (int mi = 0; mi < 2; mi++)
                    #pragma unroll
                    for (int ni = 0; ni < 4; ni++)
                        mma_f16(acc[mi][ni], a[mi], b[ni][0], b[ni][1]);
            }
        }

        // ---- register-resident LSTM epilogue ----
        cp_wait<0>();   // this thread's xproj slice (prefetched pre-barrier)
        __half* houtT = g_h16T + (size_t)((t + 1) & 1) * (H_ * HTP);
        const float* xps = (const float*)(sm + XP_OFF + (t & 1) * XP_SZ);
        #pragma unroll
        for (int mi = 0; mi < 2; mi++)
            #pragma unroll
            for (int ro = 0; ro < 2; ro++) {
                int b  = w * 32 + mi * 16 + ro * 8 + (lane >> 2);
                int q2 = (lane & 3) * 2;
                const float* xpb = xps + b * 34;
                int idx = b * H_ + col0 + q2;
                float2 cold = *(const float2*)(g_c + idx);
                float cv[2], hv[2];
                #pragma unroll
                for (int j = 0; j < 2; j++) {
                    int f = ro * 2 + j;
                    float gi = acc[mi][0][f] + xpb[q2 + j];
                    float gf = acc[mi][1][f] + xpb[8 + q2 + j];
                    float gg = acc[mi][2][f] + xpb[16 + q2 + j];
                    float go = acc[mi][3][f] + xpb[24 + q2 + j];
                    float it = sigmoidf_(gi);
                    float ft = sigmoidf_(gf);
                    float gt = tanhf(gg);
                    float ot = sigmoidf_(go);
                    float c  = ft * (j ? cold.y : cold.x) + it * gt;
                    cv[j] = c;
                    hv[j] = ot * tanhf(c);
                }
                *(float2*)(g_c + idx) = make_float2(cv[0], cv[1]);
                houtT[(col0 + q2) * HTP + b]     = __float2half(hv[0]);
                houtT[(col0 + q2 + 1) * HTP + b] = __float2half(hv[1]);
                if (t == T_ - 1)
                    *(float2*)(g_h + idx) = make_float2(hv[0], hv[1]);
            }

        // ---- prefetch next step's xproj slice (h-independent) ----
        if (t < T_ - 1) {
            prefetch_xp(sbase, t + 1, (t + 1) & 1, col0);
            cp_commit();
        }

        // ---- software grid barrier ----
        __syncthreads();
        if (tid == 0) {
            __threadfence();
            atomicAdd(&g_bar, 1u);
            unsigned tgt = (unsigned)NCTA * (t + 1);
            unsigned v;
            do {
                asm volatile("ld.acquire.gpu.u32 %0, [%1];" : "=r"(v) : "l"(&g_bar));
            } while (v < tgt);
        }
        __syncthreads();
    }
}

// ---------------------------------------------------------------------------
// Logits GEMM (fp32): C[128,1024] = g_h @ Whp^T + bhp
// ---------------------------------------------------------------------------
__global__ __launch_bounds__(256)
void logits_gemm_kernel(const float* __restrict__ Bm,
                        const float* __restrict__ bias)
{
    __shared__ float As[16][65];
    __shared__ float Bs[16][65];

    const int bn = blockIdx.x;
    const int bm = blockIdx.y;
    const int tid = threadIdx.x;
    const int tx = tid & 15;
    const int ty = tid >> 4;

    const float* Ab = g_h + (size_t)bm * 64 * H_;
    const float* Bb = Bm  + (size_t)bn * 64 * H_;

    const int lrow = tid >> 2;
    const int lk   = (tid & 3) * 4;

    float acc[4][4];
    #pragma unroll
    for (int i = 0; i < 4; i++)
        #pragma unroll
        for (int j = 0; j < 4; j++) acc[i][j] = 0.f;

    for (int k0 = 0; k0 < H_; k0 += 16) {
        float4 av = *(const float4*)(Ab + (size_t)lrow * H_ + k0 + lk);
        float4 bv = *(const float4*)(Bb + (size_t)lrow * H_ + k0 + lk);
        As[lk + 0][lrow] = av.x; As[lk + 1][lrow] = av.y;
        As[lk + 2][lrow] = av.z; As[lk + 3][lrow] = av.w;
        Bs[lk + 0][lrow] = bv.x; Bs[lk + 1][lrow] = bv.y;
        Bs[lk + 2][lrow] = bv.z; Bs[lk + 3][lrow] = bv.w;
        __syncthreads();

        #pragma unroll
        for (int kk = 0; kk < 16; kk++) {
            float am[4], bnv[4];
            #pragma unroll
            for (int i = 0; i < 4; i++) am[i]  = As[kk][ty * 4 + i];
            #pragma unroll
            for (int j = 0; j < 4; j++) bnv[j] = Bs[kk][tx * 4 + j];
            #pragma unroll
            for (int i = 0; i < 4; i++)
                #pragma unroll
                for (int j = 0; j < 4; j++)
                    acc[i][j] = fmaf(am[i], bnv[j], acc[i][j]);
        }
        __syncthreads();
    }

    const int row0 = bm * 64 + ty * 4;
    const int col0 = bn * 64 + tx * 4;
    #pragma unroll
    for (int i = 0; i < 4; i++)
        #pragma unroll
        for (int j = 0; j < 4; j++)
            g_logits[(size_t)(row0 + i) * O_ + col0 + j] = acc[i][j] + bias[col0 + j];
}

// ---------------------------------------------------------------------------
// Softmax rows -> output
// ---------------------------------------------------------------------------
__global__ __launch_bounds__(256)
void softmax_kernel(float* __restrict__ out)
{
    __shared__ float red[256];
    const int b = blockIdx.x;
    const int tid = threadIdx.x;
    const float* lr = g_logits + (size_t)b * O_;

    float m = -INFINITY;
    for (int i = tid; i < O_; i += 256) m = fmaxf(m, lr[i]);
    red[tid] = m; __syncthreads();
    for (int s = 128; s > 0; s >>= 1) {
        if (tid < s) red[tid] = fmaxf(red[tid], red[tid + s]);
        __syncthreads();
    }
    m = red[0]; __syncthreads();

    float sum = 0.f;
    for (int i = tid; i < O_; i += 256) sum += expf(lr[i] - m);
    red[tid] = sum; __syncthreads();
    for (int s = 128; s > 0; s >>= 1) {
        if (tid < s) red[tid] += red[tid + s];
        __syncthreads();
    }
    float inv = 1.f / red[0];

    for (int i = tid; i < O_; i += 256)
        out[(size_t)b * O_ + i] = expf(lr[i] - m) * inv;
}

// ---------------------------------------------------------------------------
extern "C" void kernel_launch(void* const* d_in, const int* in_sizes, int n_in,
                              void* d_out, int out_size)
{
    const float* x   = (const float*)d_in[0];  // [B,T,D]
    const float* Wx  = (const float*)d_in[1];  // [4,H,D]
    const float* Wh  = (const float*)d_in[2];  // [4,H,H]
    const float* b   = (const float*)d_in[3];  // [4,H]
    const float* Whp = (const float*)d_in[4];  // [O,H]
    const float* bhp = (const float*)d_in[5];  // [O]
    float* out = (float*)d_out;

    __half *x16, *wx16, *wh16;
    cudaGetSymbolAddress((void**)&x16,  g_x16);
    cudaGetSymbolAddress((void**)&wx16, g_Wx16);
    cudaGetSymbolAddress((void**)&wh16, g_Wh16);

    // 1) conversions to fp16
    {
        int nx = B_ * T_ * D_;
        cvt16_kernel<<<(nx + 255) / 256, 256>>>(x, x16, nx);
        int nwx = G4H * D_;
        cvt16_kernel<<<(nwx + 255) / 256, 256>>>(Wx, wx16, nwx);
        int nwh = G4H * H_;
        cvt16_kernel<<<(nwh + 255) / 256, 256>>>(Wh, wh16, nwh);
    }

    // 2) xproj = x @ Wx^T + b
    {
        dim3 grid(G4H / 64, (B_ * T_) / 128);
        xproj_kernel<<<grid, 128>>>(b);
    }

    // 3) init state + barrier
    init_kernel<<<(2 * H_ * HTP + 255) / 256, 256>>>();

    // 4) persistent recurrence (all 256 steps in one launch)
    cudaFuncSetAttribute(lstm_persistent_kernel,
                         cudaFuncAttributeMaxDynamicSharedMemorySize, SMEM_LSTM);
    lstm_persistent_kernel<<<NCTA, 128, SMEM_LSTM>>>();

    // 5) logits + softmax
    {
        dim3 grid(O_ / 64, B_ / 64);
        logits_gemm_kernel<<<grid, 256>>>(Whp, bhp);
    }
    softmax_kernel<<<B_, 256>>>(out);
}

// round 7
// speedup vs baseline: 1.0427x; 1.0427x over previous
#include <cuda_runtime.h>
#include <cuda_fp16.h>
#include <math.h>
#include <stdint.h>

#define B_   128
#define T_   256
#define D_   512
#define H_   1024
#define O_   1024
#define G4H  4096
#define NCTA 128
#define HTP  136   // padded batch pitch for transposed h

// ---------------- scratch (static device globals; no allocations) ----------
__device__ float g_xproj[(size_t)B_ * T_ * G4H];   // [B,T,4,H]
__device__ float g_h[B_ * H_];
__device__ float g_logits[B_ * O_];
__device__ unsigned g_bar;

__device__ __align__(16) __half g_x16[(size_t)B_ * T_ * D_];
__device__ __align__(16) __half g_Wx16[G4H * D_];
__device__ __align__(16) __half g_Wh16[G4H * H_];
__device__ __align__(16) __half g_h16T[2 * H_ * HTP];   // ping-pong h, [k][b]

// ---------------------------------------------------------------------------
// helpers
// ---------------------------------------------------------------------------
__device__ __forceinline__ uint32_t smem_u32(const void* p) {
    return (uint32_t)__cvta_generic_to_shared(p);
}

__device__ __forceinline__ void ldsm4(uint32_t& r0, uint32_t& r1, uint32_t& r2,
                                      uint32_t& r3, uint32_t a) {
    asm volatile("ldmatrix.sync.aligned.m8n8.x4.shared.b16 {%0,%1,%2,%3}, [%4];"
                 : "=r"(r0), "=r"(r1), "=r"(r2), "=r"(r3) : "r"(a));
}

__device__ __forceinline__ void ldsm4t(uint32_t& r0, uint32_t& r1, uint32_t& r2,
                                       uint32_t& r3, uint32_t a) {
    asm volatile("ldmatrix.sync.aligned.m8n8.x4.trans.shared.b16 {%0,%1,%2,%3}, [%4];"
                 : "=r"(r0), "=r"(r1), "=r"(r2), "=r"(r3) : "r"(a));
}

__device__ __forceinline__ void mma_f16(float* c, const uint32_t* a,
                                        uint32_t b0, uint32_t b1) {
    asm volatile(
        "mma.sync.aligned.m16n8k16.row.col.f32.f16.f16.f32 "
        "{%0,%1,%2,%3}, {%4,%5,%6,%7}, {%8,%9}, {%0,%1,%2,%3};"
        : "+f"(c[0]), "+f"(c[1]), "+f"(c[2]), "+f"(c[3])
        : "r"(a[0]), "r"(a[1]), "r"(a[2]), "r"(a[3]), "r"(b0), "r"(b1));
}

__device__ __forceinline__ void cp_async16(uint32_t dst, const void* src) {
    asm volatile("cp.async.cg.shared.global [%0], [%1], 16;" :: "r"(dst), "l"(src));
}
__device__ __forceinline__ void cp_commit() {
    asm volatile("cp.async.commit_group;");
}
template <int N> __device__ __forceinline__ void cp_wait() {
    asm volatile("cp.async.wait_group %0;" :: "n"(N));
}

__device__ __forceinline__ void mbar_init(uint32_t mbar, uint32_t cnt) {
    asm volatile("mbarrier.init.shared::cta.b64 [%0], %1;" :: "r"(mbar), "r"(cnt));
}
__device__ __forceinline__ void mbar_expect_tx(uint32_t mbar, uint32_t bytes) {
    asm volatile("mbarrier.arrive.expect_tx.shared::cta.b64 _, [%0], %1;"
                 :: "r"(mbar), "r"(bytes));
}
__device__ __forceinline__ void bulk_ldg(uint32_t dst, const void* src,
                                         uint32_t bytes, uint32_t mbar) {
    asm volatile("cp.async.bulk.shared::cta.global.mbarrier::complete_tx::bytes "
                 "[%0], [%1], %2, [%3];"
                 :: "r"(dst), "l"(src), "r"(bytes), "r"(mbar) : "memory");
}
__device__ __forceinline__ void mbar_wait(uint32_t mbar, uint32_t phase) {
    asm volatile(
        "{\n\t.reg .pred p;\n\t"
        "WAIT_%=:\n\t"
        "mbarrier.try_wait.parity.acquire.cta.shared::cta.b64 p, [%0], %1;\n\t"
        "@!p bra WAIT_%=;\n\t}"
        :: "r"(mbar), "r"(phase) : "memory");
}

__device__ __forceinline__ float sigmoidf_(float x) {
    return 1.f / (1.f + __expf(-x));
}

// ---------------------------------------------------------------------------
// conversion / init kernels
// ---------------------------------------------------------------------------
__global__ void cvt16_kernel(const float* __restrict__ src,
                             __half* __restrict__ dst, int n)
{
    int i = blockIdx.x * blockDim.x + threadIdx.x;
    if (i < n) dst[i] = __float2half(src[i]);
}

__global__ void init_kernel()
{
    int i = blockIdx.x * blockDim.x + threadIdx.x;
    if (i < 2 * H_ * HTP) g_h16T[i] = __ushort_as_half((unsigned short)0);
    if (i == 0) g_bar = 0;
}

// ---------------------------------------------------------------------------
// xproj GEMM: M=32768, N=4096, K=512; CTA M128 N64 K32, 4 warps (unchanged).
// ---------------------------------------------------------------------------
__global__ __launch_bounds__(128)
void xproj_kernel(const float* __restrict__ bias)
{
    __shared__ __align__(16) __half As[128 * 40];
    __shared__ __align__(16) __half Bs[64 * 40];

    const int tid  = threadIdx.x;
    const int lane = tid & 31;
    const int w    = tid >> 5;
    const int m_off = blockIdx.y * 128;
    const int n0    = blockIdx.x * 64;

    float acc[2][8][4];
    #pragma unroll
    for (int mi = 0; mi < 2; mi++)
        #pragma unroll
        for (int ni = 0; ni < 8; ni++)
            #pragma unroll
            for (int r = 0; r < 4; r++) acc[mi][ni][r] = 0.f;

    for (int k0 = 0; k0 < D_; k0 += 32) {
        #pragma unroll
        for (int ii = 0; ii < 4; ii++) {
            int i = tid + ii * 128;
            int row = i >> 2, q = i & 3;
            *(((uint4*)(As + row * 40)) + q) =
                *((const uint4*)(g_x16 + (size_t)(m_off + row) * D_ + k0) + q);
        }
        #pragma unroll
        for (int ii = 0; ii < 2; ii++) {
            int i = tid + ii * 128;
            int rr = i >> 2, q = i & 3;
            *(((uint4*)(Bs + rr * 40)) + q) =
                *((const uint4*)(g_Wx16 + (size_t)(n0 + rr) * D_ + k0) + q);
        }
        __syncthreads();

        #pragma unroll
        for (int kk = 0; kk < 32; kk += 16) {
            uint32_t a[2][4], b[8][2];
            int arow = lane & 15;
            int acol = kk + ((lane >> 4) << 3);
            #pragma unroll
            for (int mi = 0; mi < 2; mi++) {
                uint32_t ad = smem_u32(As + (w * 32 + mi * 16 + arow) * 40 + acol);
                ldsm4(a[mi][0], a[mi][1], a[mi][2], a[mi][3], ad);
            }
            int brl = ((lane >> 4) << 3) + (lane & 7);
            int bcol = kk + (((lane >> 3) & 1) << 3);
            #pragma unroll
            for (int g = 0; g < 4; g++) {
                uint32_t bd = smem_u32(Bs + (g * 16 + brl) * 40 + bcol);
                ldsm4(b[g * 2][0], b[g * 2][1], b[g * 2 + 1][0], b[g * 2 + 1][1], bd);
            }
            #pragma unroll
            for (int mi = 0; mi < 2; mi++)
                #pragma unroll
                for (int ni = 0; ni < 8; ni++)
                    mma_f16(acc[mi][ni], a[mi], b[ni][0], b[ni][1]);
        }
        __syncthreads();
    }

    #pragma unroll
    for (int mi = 0; mi < 2; mi++) {
        #pragma unroll
        for (int ni = 0; ni < 8; ni++) {
            int grow = m_off + w * 32 + mi * 16 + (lane >> 2);
            int gcol = n0 + ni * 8 + ((lane & 3) << 1);
            float b0 = bias[gcol], b1 = bias[gcol + 1];
            float* p0 = g_xproj + (size_t)grow * G4H + gcol;
            p0[0] = acc[mi][ni][0] + b0;
            p0[1] = acc[mi][ni][1] + b1;
            float* p1 = g_xproj + (size_t)(grow + 8) * G4H + gcol;
            p1[0] = acc[mi][ni][2] + b0;
            p1[1] = acc[mi][ni][3] + b1;
        }
    }
}

// ---------------------------------------------------------------------------
// Persistent LSTM recurrence: 128 CTAs x 256 threads (8 warps, 2/SMSP).
// Warp layout 4M x 2N: warp tile m32 n16. CTA owns 8 h-cols x 4 gates
// (N=32 gate-major Wh rows resident in SMEM, 2064B pitch).
// h transposed in gmem h16T[k][b] (272B rows); K=64 chunks via cp.async.bulk
// double buffer + mbarrier. Epilogue: accumulators staged through smem gates
// buffer (N-split exchange), per-thread LSTM update with c in registers.
// ---------------------------------------------------------------------------
#define MBAR_OFF   0
#define WH_OFF     1024
#define WH_SZ      (32 * 2064)                // 66048
#define A_OFF      (WH_OFF + WH_SZ)           // 67072
#define AS_BUF_SZ  (64 * 272)                 // 17408 per buffer
#define XP_OFF     (A_OFF + 2 * AS_BUF_SZ)    // 101888
#define XP_SZ      (128 * 36 * 4)             // 18432 per buffer
#define GT_OFF     (XP_OFF + 2 * XP_SZ)       // 138752
#define GT_SZ      (128 * 33 * 4)             // 16896
#define SMEM_LSTM  (GT_OFF + GT_SZ)           // 155648

__device__ __forceinline__ void prefetch_xp(uint32_t sbase, int t, int buf,
                                            int col0)
{
    const int tid = threadIdx.x;
    #pragma unroll
    for (int ii = 0; ii < 4; ii++) {
        int u = tid + ii * 256;          // 0..1023
        int b = u >> 3;
        int g = (u >> 1) & 3;
        int half = u & 1;
        const float* src = g_xproj + (((size_t)b * T_ + t) * 4 + g) * H_
                           + col0 + half * 4;
        cp_async16(sbase + XP_OFF + buf * XP_SZ
                   + (b * 36 + g * 8 + half * 4) * 4, src);
    }
}

__global__ __launch_bounds__(256, 1)
void lstm_persistent_kernel()
{
    extern __shared__ char sm[];
    const int tid  = threadIdx.x;
    const int lane = tid & 31;
    const int w    = tid >> 5;
    const int mw   = w & 3;       // m-tile 0..3
    const int nw   = w >> 2;      // n-half 0..1
    const int col0 = blockIdx.x * 8;
    const uint32_t sbase = smem_u32(sm);

    if (tid == 0) {
        mbar_init(sbase + MBAR_OFF, 1);
        mbar_init(sbase + MBAR_OFF + 8, 1);
    }
    __syncthreads();

    // ---- resident Wh load (fp16), gate-major rows ----
    for (int i = tid; i < 4096; i += 256) {       // 16B units
        int r = i >> 7;
        int c = i & 127;
        int ng = (r >> 3) * H_ + col0 + (r & 7);
        cp_async16(sbase + WH_OFF + r * 2064 + c * 16,
                   g_Wh16 + (size_t)ng * H_ + c * 8);
    }
    prefetch_xp(sbase, 0, 0, col0);
    cp_commit();
    cp_wait<0>();
    __syncthreads();

    uint32_t ph[2] = {0, 0};
    float creg[4] = {0.f, 0.f, 0.f, 0.f};

    for (int t = 0; t < T_; ++t) {
        const __half* hin = g_h16T + (size_t)(t & 1) * (H_ * HTP);

        if (tid == 0) {
            mbar_expect_tx(sbase + MBAR_OFF, AS_BUF_SZ);
            bulk_ldg(sbase + A_OFF, hin, AS_BUF_SZ, sbase + MBAR_OFF);
        }

        float acc[2][2][4];
        #pragma unroll
        for (int mi = 0; mi < 2; mi++)
            #pragma unroll
            for (int ni = 0; ni < 2; ni++)
                #pragma unroll
                for (int r = 0; r < 4; r++) acc[mi][ni][r] = 0.f;

        for (int ch = 0; ch < 16; ++ch) {
            const int buf = ch & 1;
            mbar_wait(sbase + MBAR_OFF + buf * 8, ph[buf]);
            ph[buf] ^= 1;
            __syncthreads();

            if (ch < 15 && tid == 0) {
                const int nb = (ch + 1) & 1;
                mbar_expect_tx(sbase + MBAR_OFF + nb * 8, AS_BUF_SZ);
                bulk_ldg(sbase + A_OFF + nb * AS_BUF_SZ,
                         hin + (size_t)(ch + 1) * 64 * HTP,
                         AS_BUF_SZ, sbase + MBAR_OFF + nb * 8);
            }

            const uint32_t Abuf = sbase + A_OFF + buf * AS_BUF_SZ;
            #pragma unroll
            for (int kk = 0; kk < 64; kk += 16) {
                uint32_t a[2][4];
                int krow = kk + ((lane >> 4) << 3) + (lane & 7);
                #pragma unroll
                for (int mi = 0; mi < 2; mi++) {
                    int mcol = mw * 32 + mi * 16 + (((lane >> 3) & 1) << 3);
                    ldsm4t(a[mi][0], a[mi][1], a[mi][2], a[mi][3],
                           Abuf + krow * 272 + mcol * 2);
                }
                uint32_t b[4];
                {
                    int brow = nw * 16 + ((lane >> 4) << 3) + (lane & 7);
                    int bcol = (ch * 64 + kk + (((lane >> 3) & 1) << 3)) * 2;
                    ldsm4(b[0], b[1], b[2], b[3],
                          sbase + WH_OFF + brow * 2064 + bcol);
                }
                #pragma unroll
                for (int mi = 0; mi < 2; mi++)
                    #pragma unroll
                    for (int ni = 0; ni < 2; ni++)
                        mma_f16(acc[mi][ni], a[mi], b[ni * 2], b[ni * 2 + 1]);
            }
        }
        __syncthreads();

        // ---- stage accumulators to gates smem (N-split exchange) ----
        {
            float* gts = (float*)(sm + GT_OFF);
            #pragma unroll
            for (int mi = 0; mi < 2; mi++)
                #pragma unroll
                for (int ni = 0; ni < 2; ni++) {
                    int row = mw * 32 + mi * 16 + (lane >> 2);
                    int col = nw * 16 + ni * 8 + ((lane & 3) << 1);
                    gts[row * 33 + col]           = acc[mi][ni][0];
                    gts[row * 33 + col + 1]       = acc[mi][ni][1];
                    gts[(row + 8) * 33 + col]     = acc[mi][ni][2];
                    gts[(row + 8) * 33 + col + 1] = acc[mi][ni][3];
                }
        }
        __syncthreads();

        // ---- per-thread LSTM update: 4 cells, c in registers ----
        cp_wait<0>();   // xproj slice for this step
        __half* houtT = g_h16T + (size_t)((t + 1) & 1) * (H_ * HTP);
        const float* xps = (const float*)(sm + XP_OFF + (t & 1) * XP_SZ);
        const float* gts = (const float*)(sm + GT_OFF);
        const int hc = tid & 7;
        #pragma unroll
        for (int k = 0; k < 4; k++) {
            int b = (tid >> 3) + k * 32;
            const float* gb  = gts + b * 33;
            const float* xpb = xps + b * 36;
            float gi = gb[hc]      + xpb[hc];
            float gf = gb[8 + hc]  + xpb[8 + hc];
            float gg = gb[16 + hc] + xpb[16 + hc];
            float go = gb[24 + hc] + xpb[24 + hc];
            float it = sigmoidf_(gi);
            float ft = sigmoidf_(gf);
            float gt = tanhf(gg);
            float ot = sigmoidf_(go);
            float c  = ft * creg[k] + it * gt;
            creg[k] = c;
            float hv = ot * tanhf(c);
            houtT[(col0 + hc) * HTP + b] = __float2half(hv);
            if (t == T_ - 1) g_h[b * H_ + col0 + hc] = hv;
        }

        // ---- prefetch next step's xproj slice (h-independent) ----
        if (t < T_ - 1) {
            prefetch_xp(sbase, t + 1, (t + 1) & 1, col0);
            cp_commit();
        }

        // ---- software grid barrier ----
        __syncthreads();
        if (tid == 0) {
            __threadfence();
            atomicAdd(&g_bar, 1u);
            unsigned tgt = (unsigned)NCTA * (t + 1);
            unsigned v;
            do {
                asm volatile("ld.acquire.gpu.u32 %0, [%1];" : "=r"(v) : "l"(&g_bar));
            } while (v < tgt);
        }
        __syncthreads();
    }
}

// ---------------------------------------------------------------------------
// Logits GEMM (fp32): C[128,1024] = g_h @ Whp^T + bhp
// ---------------------------------------------------------------------------
__global__ __launch_bounds__(256)
void logits_gemm_kernel(const float* __restrict__ Bm,
                        const float* __restrict__ bias)
{
    __shared__ float As[16][65];
    __shared__ float Bs[16][65];

    const int bn = blockIdx.x;
    const int bm = blockIdx.y;
    const int tid = threadIdx.x;
    const int tx = tid & 15;
    const int ty = tid >> 4;

    const float* Ab = g_h + (size_t)bm * 64 * H_;
    const float* Bb = Bm  + (size_t)bn * 64 * H_;

    const int lrow = tid >> 2;
    const int lk   = (tid & 3) * 4;

    float acc[4][4];
    #pragma unroll
    for (int i = 0; i < 4; i++)
        #pragma unroll
        for (int j = 0; j < 4; j++) acc[i][j] = 0.f;

    for (int k0 = 0; k0 < H_; k0 += 16) {
        float4 av = *(const float4*)(Ab + (size_t)lrow * H_ + k0 + lk);
        float4 bv = *(const float4*)(Bb + (size_t)lrow * H_ + k0 + lk);
        As[lk + 0][lrow] = av.x; As[lk + 1][lrow] = av.y;
        As[lk + 2][lrow] = av.z; As[lk + 3][lrow] = av.w;
        Bs[lk + 0][lrow] = bv.x; Bs[lk + 1][lrow] = bv.y;
        Bs[lk + 2][lrow] = bv.z; Bs[lk + 3][lrow] = bv.w;
        __syncthreads();

        #pragma unroll
        for (int kk = 0; kk < 16; kk++) {
            float am[4], bnv[4];
            #pragma unroll
            for (int i = 0; i < 4; i++) am[i]  = As[kk][ty * 4 + i];
            #pragma unroll
            for (int j = 0; j < 4; j++) bnv[j] = Bs[kk][tx * 4 + j];
            #pragma unroll
            for (int i = 0; i < 4; i++)
                #pragma unroll
                for (int j = 0; j < 4; j++)
                    acc[i][j] = fmaf(am[i], bnv[j], acc[i][j]);
        }
        __syncthreads();
    }

    const int row0 = bm * 64 + ty * 4;
    const int col0 = bn * 64 + tx * 4;
    #pragma unroll
    for (int i = 0; i < 4; i++)
        #pragma unroll
        for (int j = 0; j < 4; j++)
            g_logits[(size_t)(row0 + i) * O_ + col0 + j] = acc[i][j] + bias[col0 + j];
}

// ---------------------------------------------------------------------------
// Softmax rows -> output
// ---------------------------------------------------------------------------
__global__ __launch_bounds__(256)
void softmax_kernel(float* __restrict__ out)
{
    __shared__ float red[256];
    const int b = blockIdx.x;
    const int tid = threadIdx.x;
    const float* lr = g_logits + (size_t)b * O_;

    float m = -INFINITY;
    for (int i = tid; i < O_; i += 256) m = fmaxf(m, lr[i]);
    red[tid] = m; __syncthreads();
    for (int s = 128; s > 0; s >>= 1) {
        if (tid < s) red[tid] = fmaxf(red[tid], red[tid + s]);
        __syncthreads();
    }
    m = red[0]; __syncthreads();

    float sum = 0.f;
    for (int i = tid; i < O_; i += 256) sum += expf(lr[i] - m);
    red[tid] = sum; __syncthreads();
    for (int s = 128; s > 0; s >>= 1) {
        if (tid < s) red[tid] += red[tid + s];
        __syncthreads();
    }
    float inv = 1.f / red[0];

    for (int i = tid; i < O_; i += 256)
        out[(size_t)b * O_ + i] = expf(lr[i] - m) * inv;
}

// ---------------------------------------------------------------------------
extern "C" void kernel_launch(void* const* d_in, const int* in_sizes, int n_in,
                              void* d_out, int out_size)
{
    const float* x   = (const float*)d_in[0];  // [B,T,D]
    const float* Wx  = (const float*)d_in[1];  // [4,H,D]
    const float* Wh  = (const float*)d_in[2];  // [4,H,H]
    const float* b   = (const float*)d_in[3];  // [4,H]
    const float* Whp = (const float*)d_in[4];  // [O,H]
    const float* bhp = (const float*)d_in[5];  // [O]
    float* out = (float*)d_out;

    __half *x16, *wx16, *wh16;
    cudaGetSymbolAddress((void**)&x16,  g_x16);
    cudaGetSymbolAddress((void**)&wx16, g_Wx16);
    cudaGetSymbolAddress((void**)&wh16, g_Wh16);

    // 1) conversions to fp16
    {
        int nx = B_ * T_ * D_;
        cvt16_kernel<<<(nx + 255) / 256, 256>>>(x, x16, nx);
        int nwx = G4H * D_;
        cvt16_kernel<<<(nwx + 255) / 256, 256>>>(Wx, wx16, nwx);
        int nwh = G4H * H_;
        cvt16_kernel<<<(nwh + 255) / 256, 256>>>(Wh, wh16, nwh);
    }

    // 2) xproj = x @ Wx^T + b
    {
        dim3 grid(G4H / 64, (B_ * T_) / 128);
        xproj_kernel<<<grid, 128>>>(b);
    }

    // 3) init h + barrier
    init_kernel<<<(2 * H_ * HTP + 255) / 256, 256>>>();

    // 4) persistent recurrence (all 256 steps in one launch)
    cudaFuncSetAttribute(lstm_persistent_kernel,
                         cudaFuncAttributeMaxDynamicSharedMemorySize, SMEM_LSTM);
    lstm_persistent_kernel<<<NCTA, 256, SMEM_LSTM>>>();

    // 5) logits + softmax
    {
        dim3 grid(O_ / 64, B_ / 64);
        logits_gemm_kernel<<<grid, 256>>>(Whp, bhp);
    }
    softmax_kernel<<<B_, 256>>>(out);
}

// round 8
// speedup vs baseline: 1.3561x; 1.3005x over previous
#include <cuda_runtime.h>
#include <cuda_fp16.h>
#include <math.h>
#include <stdint.h>

#define B_   128
#define T_   256
#define D_   512
#define H_   1024
#define O_   1024
#define G4H  4096
#define NCTA 128
#define HTP  136   // padded batch pitch (halfs) for transposed h; 272B rows

// ---------------- scratch (static device globals; no allocations) ----------
__device__ float g_xproj[(size_t)B_ * T_ * G4H];   // [B,T,4,H]
__device__ float g_h[B_ * H_];
__device__ float g_logits[B_ * O_];
__device__ unsigned g_flags[NCTA * 64];            // per-CTA step flags, 256B stride

__device__ __align__(16) __half g_x16[(size_t)B_ * T_ * D_];
__device__ __align__(16) __half g_Wx16[G4H * D_];
__device__ __align__(16) __half g_Wh16[G4H * H_];
__device__ __align__(16) __half g_h16T[2 * H_ * HTP];   // ping-pong h, [k][b]

// ---------------------------------------------------------------------------
// helpers
// ---------------------------------------------------------------------------
__device__ __forceinline__ uint32_t smem_u32(const void* p) {
    return (uint32_t)__cvta_generic_to_shared(p);
}

__device__ __forceinline__ void ldsm4(uint32_t& r0, uint32_t& r1, uint32_t& r2,
                                      uint32_t& r3, uint32_t a) {
    asm volatile("ldmatrix.sync.aligned.m8n8.x4.shared.b16 {%0,%1,%2,%3}, [%4];"
                 : "=r"(r0), "=r"(r1), "=r"(r2), "=r"(r3) : "r"(a));
}

__device__ __forceinline__ void ldsm4t(uint32_t& r0, uint32_t& r1, uint32_t& r2,
                                       uint32_t& r3, uint32_t a) {
    asm volatile("ldmatrix.sync.aligned.m8n8.x4.trans.shared.b16 {%0,%1,%2,%3}, [%4];"
                 : "=r"(r0), "=r"(r1), "=r"(r2), "=r"(r3) : "r"(a));
}

__device__ __forceinline__ void mma_f16(float* c, const uint32_t* a,
                                        uint32_t b0, uint32_t b1) {
    asm volatile(
        "mma.sync.aligned.m16n8k16.row.col.f32.f16.f16.f32 "
        "{%0,%1,%2,%3}, {%4,%5,%6,%7}, {%8,%9}, {%0,%1,%2,%3};"
        : "+f"(c[0]), "+f"(c[1]), "+f"(c[2]), "+f"(c[3])
        : "r"(a[0]), "r"(a[1]), "r"(a[2]), "r"(a[3]), "r"(b0), "r"(b1));
}

__device__ __forceinline__ void cp_async16(uint32_t dst, const void* src) {
    asm volatile("cp.async.cg.shared.global [%0], [%1], 16;" :: "r"(dst), "l"(src));
}
__device__ __forceinline__ void cp_commit() {
    asm volatile("cp.async.commit_group;");
}
template <int N> __device__ __forceinline__ void cp_wait() {
    asm volatile("cp.async.wait_group %0;" :: "n"(N));
}

__device__ __forceinline__ void mbar_init(uint32_t mbar, uint32_t cnt) {
    asm volatile("mbarrier.init.shared::cta.b64 [%0], %1;" :: "r"(mbar), "r"(cnt));
}
__device__ __forceinline__ void mbar_expect_tx(uint32_t mbar, uint32_t bytes) {
    asm volatile("mbarrier.arrive.expect_tx.shared::cta.b64 _, [%0], %1;"
                 :: "r"(mbar), "r"(bytes));
}
__device__ __forceinline__ void bulk_ldg(uint32_t dst, const void* src,
                                         uint32_t bytes, uint32_t mbar) {
    asm volatile("cp.async.bulk.shared::cta.global.mbarrier::complete_tx::bytes "
                 "[%0], [%1], %2, [%3];"
                 :: "r"(dst), "l"(src), "r"(bytes), "r"(mbar) : "memory");
}
__device__ __forceinline__ void mbar_wait(uint32_t mbar, uint32_t phase) {
    asm volatile(
        "{\n\t.reg .pred p;\n\t"
        "WAIT_%=:\n\t"
        "mbarrier.try_wait.parity.acquire.cta.shared::cta.b64 p, [%0], %1;\n\t"
        "@!p bra WAIT_%=;\n\t}"
        :: "r"(mbar), "r"(phase) : "memory");
}

__device__ __forceinline__ float sigmoidf_(float x) {
    return 1.f / (1.f + __expf(-x));
}

// ---------------------------------------------------------------------------
// conversion / init kernels
// ---------------------------------------------------------------------------
__global__ void cvt16_kernel(const float* __restrict__ src,
                             __half* __restrict__ dst, int n)
{
    int i = blockIdx.x * blockDim.x + threadIdx.x;
    if (i < n) dst[i] = __float2half(src[i]);
}

__global__ void init_kernel()
{
    int i = blockIdx.x * blockDim.x + threadIdx.x;
    if (i < 2 * H_ * HTP) g_h16T[i] = __ushort_as_half((unsigned short)0);
    if (i < NCTA * 64) g_flags[i] = 0;
}

// ---------------------------------------------------------------------------
// xproj GEMM: M=32768, N=4096, K=512; CTA M128 N64 K32, 4 warps (unchanged).
// ---------------------------------------------------------------------------
__global__ __launch_bounds__(128)
void xproj_kernel(const float* __restrict__ bias)
{
    __shared__ __align__(16) __half As[128 * 40];
    __shared__ __align__(16) __half Bs[64 * 40];

    const int tid  = threadIdx.x;
    const int lane = tid & 31;
    const int w    = tid >> 5;
    const int m_off = blockIdx.y * 128;
    const int n0    = blockIdx.x * 64;

    float acc[2][8][4];
    #pragma unroll
    for (int mi = 0; mi < 2; mi++)
        #pragma unroll
        for (int ni = 0; ni < 8; ni++)
            #pragma unroll
            for (int r = 0; r < 4; r++) acc[mi][ni][r] = 0.f;

    for (int k0 = 0; k0 < D_; k0 += 32) {
        #pragma unroll
        for (int ii = 0; ii < 4; ii++) {
            int i = tid + ii * 128;
            int row = i >> 2, q = i & 3;
            *(((uint4*)(As + row * 40)) + q) =
                *((const uint4*)(g_x16 + (size_t)(m_off + row) * D_ + k0) + q);
        }
        #pragma unroll
        for (int ii = 0; ii < 2; ii++) {
            int i = tid + ii * 128;
            int rr = i >> 2, q = i & 3;
            *(((uint4*)(Bs + rr * 40)) + q) =
                *((const uint4*)(g_Wx16 + (size_t)(n0 + rr) * D_ + k0) + q);
        }
        __syncthreads();

        #pragma unroll
        for (int kk = 0; kk < 32; kk += 16) {
            uint32_t a[2][4], b[8][2];
            int arow = lane & 15;
            int acol = kk + ((lane >> 4) << 3);
            #pragma unroll
            for (int mi = 0; mi < 2; mi++) {
                uint32_t ad = smem_u32(As + (w * 32 + mi * 16 + arow) * 40 + acol);
                ldsm4(a[mi][0], a[mi][1], a[mi][2], a[mi][3], ad);
            }
            int brl = ((lane >> 4) << 3) + (lane & 7);
            int bcol = kk + (((lane >> 3) & 1) << 3);
            #pragma unroll
            for (int g = 0; g < 4; g++) {
                uint32_t bd = smem_u32(Bs + (g * 16 + brl) * 40 + bcol);
                ldsm4(b[g * 2][0], b[g * 2][1], b[g * 2 + 1][0], b[g * 2 + 1][1], bd);
            }
            #pragma unroll
            for (int mi = 0; mi < 2; mi++)
                #pragma unroll
                for (int ni = 0; ni < 8; ni++)
                    mma_f16(acc[mi][ni], a[mi], b[ni][0], b[ni][1]);
        }
        __syncthreads();
    }

    #pragma unroll
    for (int mi = 0; mi < 2; mi++) {
        #pragma unroll
        for (int ni = 0; ni < 8; ni++) {
            int grow = m_off + w * 32 + mi * 16 + (lane >> 2);
            int gcol = n0 + ni * 8 + ((lane & 3) << 1);
            float b0 = bias[gcol], b1 = bias[gcol + 1];
            float* p0 = g_xproj + (size_t)grow * G4H + gcol;
            p0[0] = acc[mi][ni][0] + b0;
            p0[1] = acc[mi][ni][1] + b1;
            float* p1 = g_xproj + (size_t)(grow + 8) * G4H + gcol;
            p1[0] = acc[mi][ni][2] + b0;
            p1[1] = acc[mi][ni][3] + b1;
        }
    }
}

// ---------------------------------------------------------------------------
// Persistent LSTM recurrence: 128 CTAs x 256 threads.
// 8 warps = 4M x 2K split; warp tile m32 n32 over its K half.
// CTA owns 8 h-cols x 4 gates (N=32 gate-major Wh rows resident in SMEM).
// h transposed in gmem h16T[k][b] (272B rows); K=128 chunks (34816B each)
// via cp.async.bulk into a 3-deep ring. K-halves reduced through a smem
// buffer aliased onto A-ring slot 0 (idle at epilogue time).
// Grid sync: per-CTA release flags, parallel polling.
// ---------------------------------------------------------------------------
#define MBAR_OFF   0
#define WH_OFF     1024
#define WH_SZ      (32 * 2064)               // 66048
#define A_OFF      (WH_OFF + WH_SZ)          // 67072
#define ACH_SZ     (128 * 272)               // 34816 per ring slot
#define XP_OFF     (A_OFF + 3 * ACH_SZ)      // 171520
#define XP_SZ      (128 * 36 * 4)            // 18432 per buffer
#define GT_OFF     A_OFF                     // aliased with ring slot 0
#define SMEM_LSTM  (XP_OFF + 2 * XP_SZ)      // 208384

// prefetch next step's xproj slice; executed by threads 128..255
__device__ __forceinline__ void prefetch_xp_half(uint32_t sbase, int t, int buf,
                                                 int col0)
{
    const int tt = threadIdx.x - 128;        // 0..127
    #pragma unroll
    for (int ii = 0; ii < 8; ii++) {
        int u = tt + ii * 128;               // 0..1023
        int b = u >> 3;
        int g = (u >> 1) & 3;
        int half = u & 1;
        cp_async16(sbase + XP_OFF + buf * XP_SZ + (b * 36 + g * 8 + half * 4) * 4,
                   g_xproj + (((size_t)b * T_ + t) * 4 + g) * H_ + col0 + half * 4);
    }
}

__global__ __launch_bounds__(256, 1)
void lstm_persistent_kernel()
{
    extern __shared__ char sm[];
    const int tid  = threadIdx.x;
    const int lane = tid & 31;
    const int w    = tid >> 5;
    const int mw   = w & 3;       // m-tile 0..3
    const int kw   = w >> 2;      // k-half 0..1
    const int col0 = blockIdx.x * 8;
    const uint32_t sbase = smem_u32(sm);

    if (tid == 0) {
        #pragma unroll
        for (int i = 0; i < 3; i++) mbar_init(sbase + MBAR_OFF + i * 8, 1);
    }
    __syncthreads();

    // ---- resident Wh load (fp16), gate-major rows ----
    for (int i = tid; i < 4096; i += 256) {       // 16B units
        int r = i >> 7;
        int c = i & 127;
        int ng = (r >> 3) * H_ + col0 + (r & 7);
        cp_async16(sbase + WH_OFF + r * 2064 + c * 16,
                   g_Wh16 + (size_t)ng * H_ + c * 8);
    }
    if (tid >= 128) prefetch_xp_half(sbase, 0, 0, col0);
    cp_commit();
    cp_wait<0>();
    __syncthreads();

    uint32_t ph[3] = {0, 0, 0};
    float creg[8];
    #pragma unroll
    for (int i = 0; i < 8; i++) creg[i] = 0.f;

    for (int t = 0; t < T_; ++t) {
        const char* hin = (const char*)(g_h16T + (size_t)(t & 1) * (H_ * HTP));

        // prologue: fill the 3-deep ring
        if (tid == 0) {
            #pragma unroll
            for (int c = 0; c < 3; c++) {
                mbar_expect_tx(sbase + MBAR_OFF + c * 8, ACH_SZ);
                bulk_ldg(sbase + A_OFF + c * ACH_SZ, hin + c * ACH_SZ,
                         ACH_SZ, sbase + MBAR_OFF + c * 8);
            }
        }

        float acc[2][4][4];
        #pragma unroll
        for (int mi = 0; mi < 2; mi++)
            #pragma unroll
            for (int ni = 0; ni < 4; ni++)
                #pragma unroll
                for (int r = 0; r < 4; r++) acc[mi][ni][r] = 0.f;

        int buf = 0;
        for (int ch = 0; ch < 8; ++ch) {
            mbar_wait(sbase + MBAR_OFF + buf * 8, ph[buf]);
            ph[buf] ^= 1;

            const uint32_t Abuf = sbase + A_OFF + buf * ACH_SZ;
            #pragma unroll
            for (int kk = 0; kk < 64; kk += 16) {
                const int kloc = kw * 64 + kk;           // k within chunk
                uint32_t a[2][4];
                int krow = kloc + ((lane >> 4) << 3) + (lane & 7);
                #pragma unroll
                for (int mi = 0; mi < 2; mi++) {
                    int mcol = mw * 32 + mi * 16 + (((lane >> 3) & 1) << 3);
                    ldsm4t(a[mi][0], a[mi][1], a[mi][2], a[mi][3],
                           Abuf + krow * 272 + mcol * 2);
                }
                uint32_t b[4][2];
                const int kglob = ch * 128 + kloc;
                #pragma unroll
                for (int nh = 0; nh < 2; nh++) {
                    int brow = nh * 16 + ((lane >> 4) << 3) + (lane & 7);
                    int bcol = (kglob + (((lane >> 3) & 1) << 3)) * 2;
                    ldsm4(b[nh * 2][0], b[nh * 2][1],
                          b[nh * 2 + 1][0], b[nh * 2 + 1][1],
                          sbase + WH_OFF + brow * 2064 + bcol);
                }
                #pragma unroll
                for (int mi = 0; mi < 2; mi++)
                    #pragma unroll
                    for (int ni = 0; ni < 4; ni++)
                        mma_f16(acc[mi][ni], a[mi], b[ni][0], b[ni][1]);
            }
            __syncthreads();
            if (ch < 5 && tid == 0) {
                mbar_expect_tx(sbase + MBAR_OFF + buf * 8, ACH_SZ);
                bulk_ldg(sbase + A_OFF + buf * ACH_SZ,
                         hin + (size_t)(ch + 3) * ACH_SZ,
                         ACH_SZ, sbase + MBAR_OFF + buf * 8);
            }
            buf = (buf == 2) ? 0 : buf + 1;
        }

        // ---- K-split reduction: kw=1 warps publish partials ----
        float* gts = (float*)(sm + GT_OFF);
        if (kw == 1) {
            #pragma unroll
            for (int mi = 0; mi < 2; mi++)
                #pragma unroll
                for (int ni = 0; ni < 4; ni++) {
                    int row = mw * 32 + mi * 16 + (lane >> 2);
                    int col = ni * 8 + ((lane & 3) << 1);
                    gts[row * 33 + col]           = acc[mi][ni][0];
                    gts[row * 33 + col + 1]       = acc[mi][ni][1];
                    gts[(row + 8) * 33 + col]     = acc[mi][ni][2];
                    gts[(row + 8) * 33 + col + 1] = acc[mi][ni][3];
                }
        }
        __syncthreads();

        if (kw == 0) {
            // ---- LSTM update: 8 cells/thread, c in registers ----
            __half* houtT = g_h16T + (size_t)((t + 1) & 1) * (H_ * HTP);
            const float* xps = (const float*)(sm + XP_OFF + (t & 1) * XP_SZ);
            const int q2 = (lane & 3) << 1;
            #pragma unroll
            for (int mi = 0; mi < 2; mi++)
                #pragma unroll
                for (int ro = 0; ro < 2; ro++) {
                    int b = mw * 32 + mi * 16 + ro * 8 + (lane >> 2);
                    const float* gb  = gts + b * 33;
                    const float* xpb = xps + b * 36;
                    #pragma unroll
                    for (int j = 0; j < 2; j++) {
                        int hc = q2 + j;
                        int f  = ro * 2 + j;
                        float gi = acc[mi][0][f] + gb[hc]      + xpb[hc];
                        float gf = acc[mi][1][f] + gb[8 + hc]  + xpb[8 + hc];
                        float gg = acc[mi][2][f] + gb[16 + hc] + xpb[16 + hc];
                        float go = acc[mi][3][f] + gb[24 + hc] + xpb[24 + hc];
                        float it = sigmoidf_(gi);
                        float ft = sigmoidf_(gf);
                        float gt = tanhf(gg);
                        float ot = sigmoidf_(go);
                        int ci = mi * 4 + ro * 2 + j;
                        float c = ft * creg[ci] + it * gt;
                        creg[ci] = c;
                        float hv = ot * tanhf(c);
                        houtT[(col0 + hc) * HTP + b] = __float2half(hv);
                        if (t == T_ - 1) g_h[b * H_ + col0 + hc] = hv;
                    }
                }
        } else if (t < T_ - 1) {
            // ---- prefetch next step's xproj slice (overlaps LSTM math) ----
            prefetch_xp_half(sbase, t + 1, (t + 1) & 1, col0);
            cp_commit();
            cp_wait<0>();
        }

        // ---- grid barrier: per-CTA flags, parallel polling ----
        __syncthreads();
        if (tid == 0) {
            __threadfence();
            asm volatile("st.release.gpu.u32 [%0], %1;"
                         :: "l"(&g_flags[blockIdx.x * 64]), "r"((unsigned)(t + 1))
                         : "memory");
        }
        if (tid < NCTA) {
            unsigned v;
            do {
                asm volatile("ld.acquire.gpu.u32 %0, [%1];"
                             : "=r"(v) : "l"(&g_flags[tid * 64]));
            } while (v < (unsigned)(t + 1));
        }
        __syncthreads();
    }
}

// ---------------------------------------------------------------------------
// Logits GEMM (fp32): C[128,1024] = g_h @ Whp^T + bhp
// ---------------------------------------------------------------------------
__global__ __launch_bounds__(256)
void logits_gemm_kernel(const float* __restrict__ Bm,
                        const float* __restrict__ bias)
{
    __shared__ float As[16][65];
    __shared__ float Bs[16][65];

    const int bn = blockIdx.x;
    const int bm = blockIdx.y;
    const int tid = threadIdx.x;
    const int tx = tid & 15;
    const int ty = tid >> 4;

    const float* Ab = g_h + (size_t)bm * 64 * H_;
    const float* Bb = Bm  + (size_t)bn * 64 * H_;

    const int lrow = tid >> 2;
    const int lk   = (tid & 3) * 4;

    float acc[4][4];
    #pragma unroll
    for (int i = 0; i < 4; i++)
        #pragma unroll
        for (int j = 0; j < 4; j++) acc[i][j] = 0.f;

    for (int k0 = 0; k0 < H_; k0 += 16) {
        float4 av = *(const float4*)(Ab + (size_t)lrow * H_ + k0 + lk);
        float4 bv = *(const float4*)(Bb + (size_t)lrow * H_ + k0 + lk);
        As[lk + 0][lrow] = av.x; As[lk + 1][lrow] = av.y;
        As[lk + 2][lrow] = av.z; As[lk + 3][lrow] = av.w;
        Bs[lk + 0][lrow] = bv.x; Bs[lk + 1][lrow] = bv.y;
        Bs[lk + 2][lrow] = bv.z; Bs[lk + 3][lrow] = bv.w;
        __syncthreads();

        #pragma unroll
        for (int kk = 0; kk < 16; kk++) {
            float am[4], bnv[4];
            #pragma unroll
            for (int i = 0; i < 4; i++) am[i]  = As[kk][ty * 4 + i];
            #pragma unroll
            for (int j = 0; j < 4; j++) bnv[j] = Bs[kk][tx * 4 + j];
            #pragma unroll
            for (int i = 0; i < 4; i++)
                #pragma unroll
                for (int j = 0; j < 4; j++)
                    acc[i][j] = fmaf(am[i], bnv[j], acc[i][j]);
        }
        __syncthreads();
    }

    const int row0 = bm * 64 + ty * 4;
    const int col0 = bn * 64 + tx * 4;
    #pragma unroll
    for (int i = 0; i < 4; i++)
        #pragma unroll
        for (int j = 0; j < 4; j++)
            g_logits[(size_t)(row0 + i) * O_ + col0 + j] = acc[i][j] + bias[col0 + j];
}

// ---------------------------------------------------------------------------
// Softmax rows -> output
// ---------------------------------------------------------------------------
__global__ __launch_bounds__(256)
void softmax_kernel(float* __restrict__ out)
{
    __shared__ float red[256];
    const int b = blockIdx.x;
    const int tid = threadIdx.x;
    const float* lr = g_logits + (size_t)b * O_;

    float m = -INFINITY;
    for (int i = tid; i < O_; i += 256) m = fmaxf(m, lr[i]);
    red[tid] = m; __syncthreads();
    for (int s = 128; s > 0; s >>= 1) {
        if (tid < s) red[tid] = fmaxf(red[tid], red[tid + s]);
        __syncthreads();
    }
    m = red[0]; __syncthreads();

    float sum = 0.f;
    for (int i = tid; i < O_; i += 256) sum += expf(lr[i] - m);
    red[tid] = sum; __syncthreads();
    for (int s = 128; s > 0; s >>= 1) {
        if (tid < s) red[tid] += red[tid + s];
        __syncthreads();
    }
    float inv = 1.f / red[0];

    for (int i = tid; i < O_; i += 256)
        out[(size_t)b * O_ + i] = expf(lr[i] - m) * inv;
}

// ---------------------------------------------------------------------------
extern "C" void kernel_launch(void* const* d_in, const int* in_sizes, int n_in,
                              void* d_out, int out_size)
{
    const float* x   = (const float*)d_in[0];  // [B,T,D]
    const float* Wx  = (const float*)d_in[1];  // [4,H,D]
    const float* Wh  = (const float*)d_in[2];  // [4,H,H]
    const float* b   = (const float*)d_in[3];  // [4,H]
    const float* Whp = (const float*)d_in[4];  // [O,H]
    const float* bhp = (const float*)d_in[5];  // [O]
    float* out = (float*)d_out;

    __half *x16, *wx16, *wh16;
    cudaGetSymbolAddress((void**)&x16,  g_x16);
    cudaGetSymbolAddress((void**)&wx16, g_Wx16);
    cudaGetSymbolAddress((void**)&wh16, g_Wh16);

    // 1) conversions to fp16
    {
        int nx = B_ * T_ * D_;
        cvt16_kernel<<<(nx + 255) / 256, 256>>>(x, x16, nx);
        int nwx = G4H * D_;
        cvt16_kernel<<<(nwx + 255) / 256, 256>>>(Wx, wx16, nwx);
        int nwh = G4H * H_;
        cvt16_kernel<<<(nwh + 255) / 256, 256>>>(Wh, wh16, nwh);
    }

    // 2) xproj = x @ Wx^T + b
    {
        dim3 grid(G4H / 64, (B_ * T_) / 128);
        xproj_kernel<<<grid, 128>>>(b);
    }

    // 3) init h + flags
    init_kernel<<<(2 * H_ * HTP + 255) / 256, 256>>>();

    // 4) persistent recurrence (all 256 steps in one launch)
    cudaFuncSetAttribute(lstm_persistent_kernel,
                         cudaFuncAttributeMaxDynamicSharedMemorySize, SMEM_LSTM);
    lstm_persistent_kernel<<<NCTA, 256, SMEM_LSTM>>>();

    // 5) logits + softmax
    {
        dim3 grid(O_ / 64, B_ / 64);
        logits_gemm_kernel<<<grid, 256>>>(Whp, bhp);
    }
    softmax_kernel<<<B_, 256>>>(out);
}

// round 9
// speedup vs baseline: 1.4176x; 1.0454x over previous
#include <cuda_runtime.h>
#include <cuda_fp16.h>
#include <math.h>
#include <stdint.h>

#define B_   128
#define T_   256
#define D_   512
#define H_   1024
#define O_   1024
#define G4H  4096
#define NCTA 128
#define HTP  136   // padded batch pitch (halfs) for transposed h; 272B rows

// ---------------- scratch (static device globals; no allocations) ----------
__device__ float g_xproj[(size_t)B_ * T_ * G4H];   // [B,T,4,H]
__device__ float g_h[B_ * H_];
__device__ float g_logits[B_ * O_];
__device__ unsigned g_flags[NCTA * 64];            // per-CTA step flags, 256B stride

__device__ __align__(16) __half g_x16[(size_t)B_ * T_ * D_];
__device__ __align__(16) __half g_Wx16[G4H * D_];
__device__ __align__(16) __half g_Wh16[G4H * H_];
__device__ __align__(16) __half g_h16T[2 * H_ * HTP];   // ping-pong h, [k][b]

// ---------------------------------------------------------------------------
// helpers
// ---------------------------------------------------------------------------
__device__ __forceinline__ uint32_t smem_u32(const void* p) {
    return (uint32_t)__cvta_generic_to_shared(p);
}

__device__ __forceinline__ void ldsm4(uint32_t& r0, uint32_t& r1, uint32_t& r2,
                                      uint32_t& r3, uint32_t a) {
    asm volatile("ldmatrix.sync.aligned.m8n8.x4.shared.b16 {%0,%1,%2,%3}, [%4];"
                 : "=r"(r0), "=r"(r1), "=r"(r2), "=r"(r3) : "r"(a));
}

__device__ __forceinline__ void ldsm4t(uint32_t& r0, uint32_t& r1, uint32_t& r2,
                                       uint32_t& r3, uint32_t a) {
    asm volatile("ldmatrix.sync.aligned.m8n8.x4.trans.shared.b16 {%0,%1,%2,%3}, [%4];"
                 : "=r"(r0), "=r"(r1), "=r"(r2), "=r"(r3) : "r"(a));
}

__device__ __forceinline__ void mma_f16(float* c, const uint32_t* a,
                                        uint32_t b0, uint32_t b1) {
    asm volatile(
        "mma.sync.aligned.m16n8k16.row.col.f32.f16.f16.f32 "
        "{%0,%1,%2,%3}, {%4,%5,%6,%7}, {%8,%9}, {%0,%1,%2,%3};"
        : "+f"(c[0]), "+f"(c[1]), "+f"(c[2]), "+f"(c[3])
        : "r"(a[0]), "r"(a[1]), "r"(a[2]), "r"(a[3]), "r"(b0), "r"(b1));
}

__device__ __forceinline__ void cp_async16(uint32_t dst, const void* src) {
    asm volatile("cp.async.cg.shared.global [%0], [%1], 16;" :: "r"(dst), "l"(src));
}
__device__ __forceinline__ void cp_commit() {
    asm volatile("cp.async.commit_group;");
}
template <int N> __device__ __forceinline__ void cp_wait() {
    asm volatile("cp.async.wait_group %0;" :: "n"(N));
}

__device__ __forceinline__ void mbar_init(uint32_t mbar, uint32_t cnt) {
    asm volatile("mbarrier.init.shared::cta.b64 [%0], %1;" :: "r"(mbar), "r"(cnt));
}
__device__ __forceinline__ void mbar_expect_tx(uint32_t mbar, uint32_t bytes) {
    asm volatile("mbarrier.arrive.expect_tx.shared::cta.b64 _, [%0], %1;"
                 :: "r"(mbar), "r"(bytes));
}
__device__ __forceinline__ void bulk_ldg(uint32_t dst, const void* src,
                                         uint32_t bytes, uint32_t mbar) {
    asm volatile("cp.async.bulk.shared::cta.global.mbarrier::complete_tx::bytes "
                 "[%0], [%1], %2, [%3];"
                 :: "r"(dst), "l"(src), "r"(bytes), "r"(mbar) : "memory");
}
__device__ __forceinline__ void mbar_wait(uint32_t mbar, uint32_t phase) {
    asm volatile(
        "{\n\t.reg .pred p;\n\t"
        "WAIT_%=:\n\t"
        "mbarrier.try_wait.parity.acquire.cta.shared::cta.b64 p, [%0], %1;\n\t"
        "@!p bra WAIT_%=;\n\t}"
        :: "r"(mbar), "r"(phase) : "memory");
}

__device__ __forceinline__ float sigmoidf_(float x) {
    return 1.f / (1.f + __expf(-x));
}

// ---------------------------------------------------------------------------
// conversion / init kernels
// ---------------------------------------------------------------------------
__global__ void cvt16_kernel(const float* __restrict__ src,
                             __half* __restrict__ dst, int n)
{
    int i = blockIdx.x * blockDim.x + threadIdx.x;
    if (i < n) dst[i] = __float2half(src[i]);
}

__global__ void init_kernel()
{
    int i = blockIdx.x * blockDim.x + threadIdx.x;
    if (i < 2 * H_ * HTP) g_h16T[i] = __ushort_as_half((unsigned short)0);
    if (i < NCTA * 64) g_flags[i] = 0;
}

// ---------------------------------------------------------------------------
// xproj GEMM v2: M=32768, N=4096, K=512.
// CTA tile M128 x N256, 256 threads = 8 warps, warp tile m64 x n64.
// cp.async double-buffered K32 chunks. Tensor-bound by design:
// per k16: STS 12KB + ldsm 32KB = 344 smem cyc < 512 tensor cyc.
// ---------------------------------------------------------------------------
#define XA_SZ  (128 * 40 * 2)   // 10240 per buffer
#define XB_SZ  (256 * 40 * 2)   // 20480 per buffer
#define SMEM_XPROJ (2 * XA_SZ + 2 * XB_SZ)   // 61440

__global__ __launch_bounds__(256, 1)
void xproj_kernel(const float* __restrict__ bias)
{
    extern __shared__ char xsm[];
    const uint32_t sbase = smem_u32(xsm);
    const uint32_t Aoff = 0;
    const uint32_t Boff = 2 * XA_SZ;

    const int tid  = threadIdx.x;
    const int lane = tid & 31;
    const int w    = tid >> 5;
    const int mw   = w & 1;        // m64 group
    const int nw   = w >> 1;       // n64 group
    const int m_off = blockIdx.y * 128;
    const int n0    = blockIdx.x * 256;

    float acc[4][8][4];
    #pragma unroll
    for (int mi = 0; mi < 4; mi++)
        #pragma unroll
        for (int ni = 0; ni < 8; ni++)
            #pragma unroll
            for (int r = 0; r < 4; r++) acc[mi][ni][r] = 0.f;

    // prologue: load chunk 0
    {
        const int k0 = 0;
        #pragma unroll
        for (int ii = 0; ii < 2; ii++) {
            int u = tid + ii * 256;            // 0..511
            int row = u >> 2, q = u & 3;
            cp_async16(sbase + Aoff + row * 80 + q * 16,
                       g_x16 + (size_t)(m_off + row) * D_ + k0 + q * 8);
        }
        #pragma unroll
        for (int ii = 0; ii < 4; ii++) {
            int u = tid + ii * 256;            // 0..1023
            int row = u >> 2, q = u & 3;
            cp_async16(sbase + Boff + row * 80 + q * 16,
                       g_Wx16 + (size_t)(n0 + row) * D_ + k0 + q * 8);
        }
        cp_commit();
    }

    int buf = 0;
    for (int ch = 0; ch < 16; ++ch) {
        if (ch < 15) {
            const int k0 = (ch + 1) * 32;
            const int nb = buf ^ 1;
            #pragma unroll
            for (int ii = 0; ii < 2; ii++) {
                int u = tid + ii * 256;
                int row = u >> 2, q = u & 3;
                cp_async16(sbase + Aoff + nb * XA_SZ + row * 80 + q * 16,
                           g_x16 + (size_t)(m_off + row) * D_ + k0 + q * 8);
            }
            #pragma unroll
            for (int ii = 0; ii < 4; ii++) {
                int u = tid + ii * 256;
                int row = u >> 2, q = u & 3;
                cp_async16(sbase + Boff + nb * XB_SZ + row * 80 + q * 16,
                           g_Wx16 + (size_t)(n0 + row) * D_ + k0 + q * 8);
            }
            cp_commit();
            cp_wait<1>();
        } else {
            cp_wait<0>();
        }
        __syncthreads();

        const uint32_t Ab = sbase + Aoff + buf * XA_SZ;
        const uint32_t Bb = sbase + Boff + buf * XB_SZ;
        #pragma unroll
        for (int kk = 0; kk < 32; kk += 16) {
            uint32_t a[4][4], b[8][2];
            int arow_l = (lane & 15);
            int acol = kk + ((lane >> 4) << 3);
            #pragma unroll
            for (int mi = 0; mi < 4; mi++) {
                int r = mw * 64 + mi * 16 + arow_l;
                ldsm4(a[mi][0], a[mi][1], a[mi][2], a[mi][3],
                      Ab + r * 80 + acol * 2);
            }
            int brow_l = ((lane >> 4) << 3) + (lane & 7);
            int bcol = kk + (((lane >> 3) & 1) << 3);
            #pragma unroll
            for (int nb2 = 0; nb2 < 4; nb2++) {
                int r = nw * 64 + nb2 * 16 + brow_l;
                ldsm4(b[nb2 * 2][0], b[nb2 * 2][1],
                      b[nb2 * 2 + 1][0], b[nb2 * 2 + 1][1],
                      Bb + r * 80 + bcol * 2);
            }
            #pragma unroll
            for (int mi = 0; mi < 4; mi++)
                #pragma unroll
                for (int ni = 0; ni < 8; ni++)
                    mma_f16(acc[mi][ni], a[mi], b[ni][0], b[ni][1]);
        }
        __syncthreads();
        buf ^= 1;
    }

    // epilogue
    #pragma unroll
    for (int mi = 0; mi < 4; mi++) {
        #pragma unroll
        for (int ni = 0; ni < 8; ni++) {
            int grow = m_off + mw * 64 + mi * 16 + (lane >> 2);
            int gcol = n0 + nw * 64 + ni * 8 + ((lane & 3) << 1);
            float b0 = bias[gcol], b1 = bias[gcol + 1];
            float* p0 = g_xproj + (size_t)grow * G4H + gcol;
            p0[0] = acc[mi][ni][0] + b0;
            p0[1] = acc[mi][ni][1] + b1;
            float* p1 = g_xproj + (size_t)(grow + 8) * G4H + gcol;
            p1[0] = acc[mi][ni][2] + b0;
            p1[1] = acc[mi][ni][3] + b1;
        }
    }
}

// ---------------------------------------------------------------------------
// Persistent LSTM recurrence: 128 CTAs x 256 threads (unchanged from R8).
// ---------------------------------------------------------------------------
#define MBAR_OFF   0
#define WH_OFF     1024
#define WH_SZ      (32 * 2064)               // 66048
#define A_OFF      (WH_OFF + WH_SZ)          // 67072
#define ACH_SZ     (128 * 272)               // 34816 per ring slot
#define XP_OFF     (A_OFF + 3 * ACH_SZ)      // 171520
#define XP_SZ      (128 * 36 * 4)            // 18432 per buffer
#define GT_OFF     A_OFF                     // aliased with ring slot 0
#define SMEM_LSTM  (XP_OFF + 2 * XP_SZ)      // 208384

__device__ __forceinline__ void prefetch_xp_half(uint32_t sbase, int t, int buf,
                                                 int col0)
{
    const int tt = threadIdx.x - 128;        // 0..127
    #pragma unroll
    for (int ii = 0; ii < 8; ii++) {
        int u = tt + ii * 128;               // 0..1023
        int b = u >> 3;
        int g = (u >> 1) & 3;
        int half = u & 1;
        cp_async16(sbase + XP_OFF + buf * XP_SZ + (b * 36 + g * 8 + half * 4) * 4,
                   g_xproj + (((size_t)b * T_ + t) * 4 + g) * H_ + col0 + half * 4);
    }
}

__global__ __launch_bounds__(256, 1)
void lstm_persistent_kernel()
{
    extern __shared__ char sm[];
    const int tid  = threadIdx.x;
    const int lane = tid & 31;
    const int w    = tid >> 5;
    const int mw   = w & 3;       // m-tile 0..3
    const int kw   = w >> 2;      // k-half 0..1
    const int col0 = blockIdx.x * 8;
    const uint32_t sbase = smem_u32(sm);

    if (tid == 0) {
        #pragma unroll
        for (int i = 0; i < 3; i++) mbar_init(sbase + MBAR_OFF + i * 8, 1);
    }
    __syncthreads();

    // ---- resident Wh load (fp16), gate-major rows ----
    for (int i = tid; i < 4096; i += 256) {       // 16B units
        int r = i >> 7;
        int c = i & 127;
        int ng = (r >> 3) * H_ + col0 + (r & 7);
        cp_async16(sbase + WH_OFF + r * 2064 + c * 16,
                   g_Wh16 + (size_t)ng * H_ + c * 8);
    }
    if (tid >= 128) prefetch_xp_half(sbase, 0, 0, col0);
    cp_commit();
    cp_wait<0>();
    __syncthreads();

    uint32_t ph[3] = {0, 0, 0};
    float creg[8];
    #pragma unroll
    for (int i = 0; i < 8; i++) creg[i] = 0.f;

    for (int t = 0; t < T_; ++t) {
        const char* hin = (const char*)(g_h16T + (size_t)(t & 1) * (H_ * HTP));

        // prologue: fill the 3-deep ring
        if (tid == 0) {
            #pragma unroll
            for (int c = 0; c < 3; c++) {
                mbar_expect_tx(sbase + MBAR_OFF + c * 8, ACH_SZ);
                bulk_ldg(sbase + A_OFF + c * ACH_SZ, hin + c * ACH_SZ,
                         ACH_SZ, sbase + MBAR_OFF + c * 8);
            }
        }

        float acc[2][4][4];
        #pragma unroll
        for (int mi = 0; mi < 2; mi++)
            #pragma unroll
            for (int ni = 0; ni < 4; ni++)
                #pragma unroll
                for (int r = 0; r < 4; r++) acc[mi][ni][r] = 0.f;

        int buf = 0;
        for (int ch = 0; ch < 8; ++ch) {
            mbar_wait(sbase + MBAR_OFF + buf * 8, ph[buf]);
            ph[buf] ^= 1;

            const uint32_t Abuf = sbase + A_OFF + buf * ACH_SZ;
            #pragma unroll
            for (int kk = 0; kk < 64; kk += 16) {
                const int kloc = kw * 64 + kk;           // k within chunk
                uint32_t a[2][4];
                int krow = kloc + ((lane >> 4) << 3) + (lane & 7);
                #pragma unroll
                for (int mi = 0; mi < 2; mi++) {
                    int mcol = mw * 32 + mi * 16 + (((lane >> 3) & 1) << 3);
                    ldsm4t(a[mi][0], a[mi][1], a[mi][2], a[mi][3],
                           Abuf + krow * 272 + mcol * 2);
                }
                uint32_t b[4][2];
                const int kglob = ch * 128 + kloc;
                #pragma unroll
                for (int nh = 0; nh < 2; nh++) {
                    int brow = nh * 16 + ((lane >> 4) << 3) + (lane & 7);
                    int bcol = (kglob + (((lane >> 3) & 1) << 3)) * 2;
                    ldsm4(b[nh * 2][0], b[nh * 2][1],
                          b[nh * 2 + 1][0], b[nh * 2 + 1][1],
                          sbase + WH_OFF + brow * 2064 + bcol);
                }
                #pragma unroll
                for (int mi = 0; mi < 2; mi++)
                    #pragma unroll
                    for (int ni = 0; ni < 4; ni++)
                        mma_f16(acc[mi][ni], a[mi], b[ni][0], b[ni][1]);
            }
            __syncthreads();
            if (ch < 5 && tid == 0) {
                mbar_expect_tx(sbase + MBAR_OFF + buf * 8, ACH_SZ);
                bulk_ldg(sbase + A_OFF + buf * ACH_SZ,
                         hin + (size_t)(ch + 3) * ACH_SZ,
                         ACH_SZ, sbase + MBAR_OFF + buf * 8);
            }
            buf = (buf == 2) ? 0 : buf + 1;
        }

        // ---- K-split reduction: kw=1 warps publish partials ----
        float* gts = (float*)(sm + GT_OFF);
        if (kw == 1) {
            #pragma unroll
            for (int mi = 0; mi < 2; mi++)
                #pragma unroll
                for (int ni = 0; ni < 4; ni++) {
                    int row = mw * 32 + mi * 16 + (lane >> 2);
                    int col = ni * 8 + ((lane & 3) << 1);
                    gts[row * 33 + col]           = acc[mi][ni][0];
                    gts[row * 33 + col + 1]       = acc[mi][ni][1];
                    gts[(row + 8) * 33 + col]     = acc[mi][ni][2];
                    gts[(row + 8) * 33 + col + 1] = acc[mi][ni][3];
                }
        }
        __syncthreads();

        if (kw == 0) {
            // ---- LSTM update: 8 cells/thread, c in registers ----
            __half* houtT = g_h16T + (size_t)((t + 1) & 1) * (H_ * HTP);
            const float* xps = (const float*)(sm + XP_OFF + (t & 1) * XP_SZ);
            const int q2 = (lane & 3) << 1;
            #pragma unroll
            for (int mi = 0; mi < 2; mi++)
                #pragma unroll
                for (int ro = 0; ro < 2; ro++) {
                    int b = mw * 32 + mi * 16 + ro * 8 + (lane >> 2);
                    const float* gb  = gts + b * 33;
                    const float* xpb = xps + b * 36;
                    #pragma unroll
                    for (int j = 0; j < 2; j++) {
                        int hc = q2 + j;
                        int f  = ro * 2 + j;
                        float gi = acc[mi][0][f] + gb[hc]      + xpb[hc];
                        float gf = acc[mi][1][f] + gb[8 + hc]  + xpb[8 + hc];
                        float gg = acc[mi][2][f] + gb[16 + hc] + xpb[16 + hc];
                        float go = acc[mi][3][f] + gb[24 + hc] + xpb[24 + hc];
                        float it = sigmoidf_(gi);
                        float ft = sigmoidf_(gf);
                        float gt = tanhf(gg);
                        float ot = sigmoidf_(go);
                        int ci = mi * 4 + ro * 2 + j;
                        float c = ft * creg[ci] + it * gt;
                        creg[ci] = c;
                        float hv = ot * tanhf(c);
                        houtT[(col0 + hc) * HTP + b] = __float2half(hv);
                        if (t == T_ - 1) g_h[b * H_ + col0 + hc] = hv;
                    }
                }
        } else if (t < T_ - 1) {
            // ---- prefetch next step's xproj slice (overlaps LSTM math) ----
            prefetch_xp_half(sbase, t + 1, (t + 1) & 1, col0);
            cp_commit();
            cp_wait<0>();
        }

        // ---- grid barrier: per-CTA flags, parallel polling ----
        __syncthreads();
        if (tid == 0) {
            __threadfence();
            asm volatile("st.release.gpu.u32 [%0], %1;"
                         :: "l"(&g_flags[blockIdx.x * 64]), "r"((unsigned)(t + 1))
                         : "memory");
        }
        if (tid < NCTA) {
            unsigned v;
            do {
                asm volatile("ld.acquire.gpu.u32 %0, [%1];"
                             : "=r"(v) : "l"(&g_flags[tid * 64]));
            } while (v < (unsigned)(t + 1));
        }
        __syncthreads();
    }
}

// ---------------------------------------------------------------------------
// Logits GEMM (fp32): C[128,1024] = g_h @ Whp^T + bhp
// ---------------------------------------------------------------------------
__global__ __launch_bounds__(256)
void logits_gemm_kernel(const float* __restrict__ Bm,
                        const float* __restrict__ bias)
{
    __shared__ float As[16][65];
    __shared__ float Bs[16][65];

    const int bn = blockIdx.x;
    const int bm = blockIdx.y;
    const int tid = threadIdx.x;
    const int tx = tid & 15;
    const int ty = tid >> 4;

    const float* Ab = g_h + (size_t)bm * 64 * H_;
    const float* Bb = Bm  + (size_t)bn * 64 * H_;

    const int lrow = tid >> 2;
    const int lk   = (tid & 3) * 4;

    float acc[4][4];
    #pragma unroll
    for (int i = 0; i < 4; i++)
        #pragma unroll
        for (int j = 0; j < 4; j++) acc[i][j] = 0.f;

    for (int k0 = 0; k0 < H_; k0 += 16) {
        float4 av = *(const float4*)(Ab + (size_t)lrow * H_ + k0 + lk);
        float4 bv = *(const float4*)(Bb + (size_t)lrow * H_ + k0 + lk);
        As[lk + 0][lrow] = av.x; As[lk + 1][lrow] = av.y;
        As[lk + 2][lrow] = av.z; As[lk + 3][lrow] = av.w;
        Bs[lk + 0][lrow] = bv.x; Bs[lk + 1][lrow] = bv.y;
        Bs[lk + 2][lrow] = bv.z; Bs[lk + 3][lrow] = bv.w;
        __syncthreads();

        #pragma unroll
        for (int kk = 0; kk < 16; kk++) {
            float am[4], bnv[4];
            #pragma unroll
            for (int i = 0; i < 4; i++) am[i]  = As[kk][ty * 4 + i];
            #pragma unroll
            for (int j = 0; j < 4; j++) bnv[j] = Bs[kk][tx * 4 + j];
            #pragma unroll
            for (int i = 0; i < 4; i++)
                #pragma unroll
                for (int j = 0; j < 4; j++)
                    acc[i][j] = fmaf(am[i], bnv[j], acc[i][j]);
        }
        __syncthreads();
    }

    const int row0 = bm * 64 + ty * 4;
    const int col0 = bn * 64 + tx * 4;
    #pragma unroll
    for (int i = 0; i < 4; i++)
        #pragma unroll
        for (int j = 0; j < 4; j++)
            g_logits[(size_t)(row0 + i) * O_ + col0 + j] = acc[i][j] + bias[col0 + j];
}

// ---------------------------------------------------------------------------
// Softmax rows -> output
// ---------------------------------------------------------------------------
__global__ __launch_bounds__(256)
void softmax_kernel(float* __restrict__ out)
{
    __shared__ float red[256];
    const int b = blockIdx.x;
    const int tid = threadIdx.x;
    const float* lr = g_logits + (size_t)b * O_;

    float m = -INFINITY;
    for (int i = tid; i < O_; i += 256) m = fmaxf(m, lr[i]);
    red[tid] = m; __syncthreads();
    for (int s = 128; s > 0; s >>= 1) {
        if (tid < s) red[tid] = fmaxf(red[tid], red[tid + s]);
        __syncthreads();
    }
    m = red[0]; __syncthreads();

    float sum = 0.f;
    for (int i = tid; i < O_; i += 256) sum += expf(lr[i] - m);
    red[tid] = sum; __syncthreads();
    for (int s = 128; s > 0; s >>= 1) {
        if (tid < s) red[tid] += red[tid + s];
        __syncthreads();
    }
    float inv = 1.f / red[0];

    for (int i = tid; i < O_; i += 256)
        out[(size_t)b * O_ + i] = expf(lr[i] - m) * inv;
}

// ---------------------------------------------------------------------------
extern "C" void kernel_launch(void* const* d_in, const int* in_sizes, int n_in,
                              void* d_out, int out_size)
{
    const float* x   = (const float*)d_in[0];  // [B,T,D]
    const float* Wx  = (const float*)d_in[1];  // [4,H,D]
    const float* Wh  = (const float*)d_in[2];  // [4,H,H]
    const float* b   = (const float*)d_in[3];  // [4,H]
    const float* Whp = (const float*)d_in[4];  // [O,H]
    const float* bhp = (const float*)d_in[5];  // [O]
    float* out = (float*)d_out;

    __half *x16, *wx16, *wh16;
    cudaGetSymbolAddress((void**)&x16,  g_x16);
    cudaGetSymbolAddress((void**)&wx16, g_Wx16);
    cudaGetSymbolAddress((void**)&wh16, g_Wh16);

    // 1) conversions to fp16
    {
        int nx = B_ * T_ * D_;
        cvt16_kernel<<<(nx + 255) / 256, 256>>>(x, x16, nx);
        int nwx = G4H * D_;
        cvt16_kernel<<<(nwx + 255) / 256, 256>>>(Wx, wx16, nwx);
        int nwh = G4H * H_;
        cvt16_kernel<<<(nwh + 255) / 256, 256>>>(Wh, wh16, nwh);
    }

    // 2) xproj = x @ Wx^T + b  (v2: 128x256 tiles, m64n64 warps)
    {
        cudaFuncSetAttribute(xproj_kernel,
                             cudaFuncAttributeMaxDynamicSharedMemorySize,
                             SMEM_XPROJ);
        dim3 grid(G4H / 256, (B_ * T_) / 128);
        xproj_kernel<<<grid, 256, SMEM_XPROJ>>>(b);
    }

    // 3) init h + flags
    init_kernel<<<(2 * H_ * HTP + 255) / 256, 256>>>();

    // 4) persistent recurrence (all 256 steps in one launch)
    cudaFuncSetAttribute(lstm_persistent_kernel,
                         cudaFuncAttributeMaxDynamicSharedMemorySize, SMEM_LSTM);
    lstm_persistent_kernel<<<NCTA, 256, SMEM_LSTM>>>();

    // 5) logits + softmax
    {
        dim3 grid(O_ / 64, B_ / 64);
        logits_gemm_kernel<<<grid, 256>>>(Whp, bhp);
    }
    softmax_kernel<<<B_, 256>>>(out);
}

// round 11
// speedup vs baseline: 1.5016x; 1.0593x over previous
#include <cuda_runtime.h>
#include <cuda_fp16.h>
#include <math.h>
#include <stdint.h>

#define B_   128
#define T_   256
#define D_   512
#define H_   1024
#define O_   1024
#define G4H  4096
#define NCTA 128
#define HTP  136   // padded batch pitch (halfs) for transposed h; 272B rows

// ---------------- scratch (static device globals; no allocations) ----------
__device__ __align__(16) __half g_xproj[(size_t)B_ * T_ * G4H];  // fp16
__device__ float g_h[B_ * H_];
__device__ float g_logits[B_ * O_];
__device__ unsigned g_flags[NCTA * 64];            // per-CTA step flags, 256B stride

__device__ __align__(16) __half g_x16[(size_t)B_ * T_ * D_];
__device__ __align__(16) __half g_Wx16[G4H * D_];
__device__ __align__(16) __half g_Wh16[G4H * H_];
__device__ __align__(16) __half g_h16T[2 * H_ * HTP];   // ping-pong h, [k][b]

// ---------------------------------------------------------------------------
// helpers
// ---------------------------------------------------------------------------
__device__ __forceinline__ uint32_t smem_u32(const void* p) {
    return (uint32_t)__cvta_generic_to_shared(p);
}

__device__ __forceinline__ void ldsm4(uint32_t& r0, uint32_t& r1, uint32_t& r2,
                                      uint32_t& r3, uint32_t a) {
    asm volatile("ldmatrix.sync.aligned.m8n8.x4.shared.b16 {%0,%1,%2,%3}, [%4];"
                 : "=r"(r0), "=r"(r1), "=r"(r2), "=r"(r3) : "r"(a));
}

__device__ __forceinline__ void ldsm4t(uint32_t& r0, uint32_t& r1, uint32_t& r2,
                                       uint32_t& r3, uint32_t a) {
    asm volatile("ldmatrix.sync.aligned.m8n8.x4.trans.shared.b16 {%0,%1,%2,%3}, [%4];"
                 : "=r"(r0), "=r"(r1), "=r"(r2), "=r"(r3) : "r"(a));
}

__device__ __forceinline__ void mma_f16(float* c, const uint32_t* a,
                                        uint32_t b0, uint32_t b1) {
    asm volatile(
        "mma.sync.aligned.m16n8k16.row.col.f32.f16.f16.f32 "
        "{%0,%1,%2,%3}, {%4,%5,%6,%7}, {%8,%9}, {%0,%1,%2,%3};"
        : "+f"(c[0]), "+f"(c[1]), "+f"(c[2]), "+f"(c[3])
        : "r"(a[0]), "r"(a[1]), "r"(a[2]), "r"(a[3]), "r"(b0), "r"(b1));
}

__device__ __forceinline__ void cp_async16(uint32_t dst, const void* src) {
    asm volatile("cp.async.cg.shared.global [%0], [%1], 16;" :: "r"(dst), "l"(src));
}
__device__ __forceinline__ void cp_commit() {
    asm volatile("cp.async.commit_group;");
}
template <int N> __device__ __forceinline__ void cp_wait() {
    asm volatile("cp.async.wait_group %0;" :: "n"(N));
}

__device__ __forceinline__ void mbar_init(uint32_t mbar, uint32_t cnt) {
    asm volatile("mbarrier.init.shared::cta.b64 [%0], %1;" :: "r"(mbar), "r"(cnt));
}
__device__ __forceinline__ void mbar_expect_tx(uint32_t mbar, uint32_t bytes) {
    asm volatile("mbarrier.arrive.expect_tx.shared::cta.b64 _, [%0], %1;"
                 :: "r"(mbar), "r"(bytes));
}
__device__ __forceinline__ void mbar_arrive(uint32_t mbar) {
    asm volatile("mbarrier.arrive.release.cta.shared::cta.b64 _, [%0];"
                 :: "r"(mbar) : "memory");
}
__device__ __forceinline__ void bulk_ldg(uint32_t dst, const void* src,
                                         uint32_t bytes, uint32_t mbar) {
    asm volatile("cp.async.bulk.shared::cta.global.mbarrier::complete_tx::bytes "
                 "[%0], [%1], %2, [%3];"
                 :: "r"(dst), "l"(src), "r"(bytes), "r"(mbar) : "memory");
}
__device__ __forceinline__ void mbar_wait(uint32_t mbar, uint32_t phase) {
    asm volatile(
        "{\n\t.reg .pred p;\n\t"
        "WAIT_%=:\n\t"
        "mbarrier.try_wait.parity.acquire.cta.shared::cta.b64 p, [%0], %1;\n\t"
        "@!p bra WAIT_%=;\n\t}"
        :: "r"(mbar), "r"(phase) : "memory");
}

__device__ __forceinline__ float sigmoidf_(float x) {
    return 1.f / (1.f + __expf(-x));
}

// ---------------------------------------------------------------------------
// conversion / init kernels
// ---------------------------------------------------------------------------
__global__ void cvt16_kernel(const float* __restrict__ src,
                             __half* __restrict__ dst, int n)
{
    int i = blockIdx.x * blockDim.x + threadIdx.x;
    if (i < n) dst[i] = __float2half(src[i]);
}

__global__ void init_kernel()
{
    int i = blockIdx.x * blockDim.x + threadIdx.x;
    if (i < 2 * H_ * HTP) g_h16T[i] = __ushort_as_half((unsigned short)0);
    if (i < NCTA * 64) g_flags[i] = 0;
}

// ---------------------------------------------------------------------------
// xproj GEMM v2 (fp16 output): M=32768, N=4096, K=512.
// CTA tile M128 x N256, 256 threads = 8 warps, warp tile m64 x n64.
// ---------------------------------------------------------------------------
#define XA_SZ  (128 * 40 * 2)   // 10240 per buffer
#define XB_SZ  (256 * 40 * 2)   // 20480 per buffer
#define SMEM_XPROJ (2 * XA_SZ + 2 * XB_SZ)   // 61440

__global__ __launch_bounds__(256, 1)
void xproj_kernel(const float* __restrict__ bias)
{
    extern __shared__ char xsm[];
    const uint32_t sbase = smem_u32(xsm);
    const uint32_t Aoff = 0;
    const uint32_t Boff = 2 * XA_SZ;

    const int tid  = threadIdx.x;
    const int lane = tid & 31;
    const int w    = tid >> 5;
    const int mw   = w & 1;        // m64 group
    const int nw   = w >> 1;       // n64 group
    const int m_off = blockIdx.y * 128;
    const int n0    = blockIdx.x * 256;

    float acc[4][8][4];
    #pragma unroll
    for (int mi = 0; mi < 4; mi++)
        #pragma unroll
        for (int ni = 0; ni < 8; ni++)
            #pragma unroll
            for (int r = 0; r < 4; r++) acc[mi][ni][r] = 0.f;

    // prologue: load chunk 0
    {
        #pragma unroll
        for (int ii = 0; ii < 2; ii++) {
            int u = tid + ii * 256;
            int row = u >> 2, q = u & 3;
            cp_async16(sbase + Aoff + row * 80 + q * 16,
                       g_x16 + (size_t)(m_off + row) * D_ + q * 8);
        }
        #pragma unroll
        for (int ii = 0; ii < 4; ii++) {
            int u = tid + ii * 256;
            int row = u >> 2, q = u & 3;
            cp_async16(sbase + Boff + row * 80 + q * 16,
                       g_Wx16 + (size_t)(n0 + row) * D_ + q * 8);
        }
        cp_commit();
    }

    int buf = 0;
    for (int ch = 0; ch < 16; ++ch) {
        if (ch < 15) {
            const int k0 = (ch + 1) * 32;
            const int nb = buf ^ 1;
            #pragma unroll
            for (int ii = 0; ii < 2; ii++) {
                int u = tid + ii * 256;
                int row = u >> 2, q = u & 3;
                cp_async16(sbase + Aoff + nb * XA_SZ + row * 80 + q * 16,
                           g_x16 + (size_t)(m_off + row) * D_ + k0 + q * 8);
            }
            #pragma unroll
            for (int ii = 0; ii < 4; ii++) {
                int u = tid + ii * 256;
                int row = u >> 2, q = u & 3;
                cp_async16(sbase + Boff + nb * XB_SZ + row * 80 + q * 16,
                           g_Wx16 + (size_t)(n0 + row) * D_ + k0 + q * 8);
            }
            cp_commit();
            cp_wait<1>();
        } else {
            cp_wait<0>();
        }
        __syncthreads();

        const uint32_t Ab = sbase + Aoff + buf * XA_SZ;
        const uint32_t Bb = sbase + Boff + buf * XB_SZ;
        #pragma unroll
        for (int kk = 0; kk < 32; kk += 16) {
            uint32_t a[4][4], b[8][2];
            int arow_l = (lane & 15);
            int acol = kk + ((lane >> 4) << 3);
            #pragma unroll
            for (int mi = 0; mi < 4; mi++) {
                int r = mw * 64 + mi * 16 + arow_l;
                ldsm4(a[mi][0], a[mi][1], a[mi][2], a[mi][3],
                      Ab + r * 80 + acol * 2);
            }
            int brow_l = ((lane >> 4) << 3) + (lane & 7);
            int bcol = kk + (((lane >> 3) & 1) << 3);
            #pragma unroll
            for (int nb2 = 0; nb2 < 4; nb2++) {
                int r = nw * 64 + nb2 * 16 + brow_l;
                ldsm4(b[nb2 * 2][0], b[nb2 * 2][1],
                      b[nb2 * 2 + 1][0], b[nb2 * 2 + 1][1],
                      Bb + r * 80 + bcol * 2);
            }
            #pragma unroll
            for (int mi = 0; mi < 4; mi++)
                #pragma unroll
                for (int ni = 0; ni < 8; ni++)
                    mma_f16(acc[mi][ni], a[mi], b[ni][0], b[ni][1]);
        }
        __syncthreads();
        buf ^= 1;
    }

    // epilogue: fp16 stores
    #pragma unroll
    for (int mi = 0; mi < 4; mi++) {
        #pragma unroll
        for (int ni = 0; ni < 8; ni++) {
            int grow = m_off + mw * 64 + mi * 16 + (lane >> 2);
            int gcol = n0 + nw * 64 + ni * 8 + ((lane & 3) << 1);
            float b0 = bias[gcol], b1 = bias[gcol + 1];
            *(__half2*)(g_xproj + (size_t)grow * G4H + gcol) =
                __floats2half2_rn(acc[mi][ni][0] + b0, acc[mi][ni][1] + b1);
            *(__half2*)(g_xproj + (size_t)(grow + 8) * G4H + gcol) =
                __floats2half2_rn(acc[mi][ni][2] + b0, acc[mi][ni][3] + b1);
        }
    }
}

// ---------------------------------------------------------------------------
// Persistent LSTM recurrence: 128 CTAs x 256 threads.
// 8 warps = 4M x 2K split; warp tile m32 n32 over its K half.
// h via cp.async.bulk into 3-deep ring; FULL/CONS mbarrier warp-slip
// pipeline (no per-chunk CTA sync). Grid sync: per-CTA flags.
// xproj staged in smem with 40-half (80B) batch pitch -> 16B-aligned cp.async.
// ---------------------------------------------------------------------------
#define MB_FULL(i) ((i) * 8)
#define MB_CONS(i) (24 + (i) * 8)
#define WH_OFF     1024
#define WH_SZ      (32 * 2064)               // 66048
#define A_OFF      (WH_OFF + WH_SZ)          // 67072
#define ACH_SZ     (128 * 272)               // 34816 per ring slot
#define XP_OFF     (A_OFF + 3 * ACH_SZ)      // 171520
#define XP_SZ      (128 * 40 * 2)            // 10240 per buffer (fp16, 80B pitch)
#define GT_OFF     A_OFF                     // aliased with ring slot 0
#define SMEM_LSTM  (XP_OFF + 2 * XP_SZ)      // 192000

// prefetch next step's xproj slice (fp16); executed by threads 128..255
__device__ __forceinline__ void prefetch_xp_half(uint32_t sbase, int t, int buf,
                                                 int col0)
{
    const int tt = threadIdx.x - 128;        // 0..127
    #pragma unroll
    for (int ii = 0; ii < 4; ii++) {
        int u = tt + ii * 128;               // 0..511
        int b = u >> 2;
        int g = u & 3;
        // smem offset: b*80 + g*16 bytes — 16B aligned for all b, g
        cp_async16(sbase + XP_OFF + buf * XP_SZ + b * 80 + g * 16,
                   g_xproj + (((size_t)b * T_ + t) * 4 + g) * H_ + col0);
    }
}

__global__ __launch_bounds__(256, 1)
void lstm_persistent_kernel()
{
    extern __shared__ char sm[];
    const int tid  = threadIdx.x;
    const int lane = tid & 31;
    const int w    = tid >> 5;
    const int mw   = w & 3;       // m-tile 0..3
    const int kw   = w >> 2;      // k-half 0..1
    const int col0 = blockIdx.x * 8;
    const uint32_t sbase = smem_u32(sm);

    if (tid == 0) {
        #pragma unroll
        for (int i = 0; i < 3; i++) {
            mbar_init(sbase + MB_FULL(i), 1);
            mbar_init(sbase + MB_CONS(i), 8);   // one arrive per warp
        }
    }
    __syncthreads();

    // ---- resident Wh load (fp16), gate-major rows ----
    for (int i = tid; i < 4096; i += 256) {       // 16B units
        int r = i >> 7;
        int c = i & 127;
        int ng = (r >> 3) * H_ + col0 + (r & 7);
        cp_async16(sbase + WH_OFF + r * 2064 + c * 16,
                   g_Wh16 + (size_t)ng * H_ + c * 8);
    }
    if (tid >= 128) prefetch_xp_half(sbase, 0, 0, col0);
    cp_commit();
    cp_wait<0>();
    __syncthreads();

    uint32_t fph[3] = {0, 0, 0};
    uint32_t cph[3] = {0, 0, 0};
    float creg[8];
    #pragma unroll
    for (int i = 0; i < 8; i++) creg[i] = 0.f;

    for (int t = 0; t < T_; ++t) {
        const char* hin = (const char*)(g_h16T + (size_t)(t & 1) * (H_ * HTP));

        // prologue: fill the 3-deep ring (slots free: end-of-step sync+barrier)
        if (tid == 0) {
            #pragma unroll
            for (int c = 0; c < 3; c++) {
                mbar_expect_tx(sbase + MB_FULL(c), ACH_SZ);
                bulk_ldg(sbase + A_OFF + c * ACH_SZ, hin + c * ACH_SZ,
                         ACH_SZ, sbase + MB_FULL(c));
            }
        }

        float acc[2][4][4];
        #pragma unroll
        for (int mi = 0; mi < 2; mi++)
            #pragma unroll
            for (int ni = 0; ni < 4; ni++)
                #pragma unroll
                for (int r = 0; r < 4; r++) acc[mi][ni][r] = 0.f;

        int buf = 0;
        for (int ch = 0; ch < 8; ++ch) {
            mbar_wait(sbase + MB_FULL(buf), fph[buf]);
            fph[buf] ^= 1;

            const uint32_t Abuf = sbase + A_OFF + buf * ACH_SZ;
            #pragma unroll
            for (int kk = 0; kk < 64; kk += 16) {
                const int kloc = kw * 64 + kk;           // k within chunk
                uint32_t a[2][4];
                int krow = kloc + ((lane >> 4) << 3) + (lane & 7);
                #pragma unroll
                for (int mi = 0; mi < 2; mi++) {
                    int mcol = mw * 32 + mi * 16 + (((lane >> 3) & 1) << 3);
                    ldsm4t(a[mi][0], a[mi][1], a[mi][2], a[mi][3],
                           Abuf + krow * 272 + mcol * 2);
                }
                uint32_t b[4][2];
                const int kglob = ch * 128 + kloc;
                #pragma unroll
                for (int nh = 0; nh < 2; nh++) {
                    int brow = nh * 16 + ((lane >> 4) << 3) + (lane & 7);
                    int bcol = (kglob + (((lane >> 3) & 1) << 3)) * 2;
                    ldsm4(b[nh * 2][0], b[nh * 2][1],
                          b[nh * 2 + 1][0], b[nh * 2 + 1][1],
                          sbase + WH_OFF + brow * 2064 + bcol);
                }
                #pragma unroll
                for (int mi = 0; mi < 2; mi++)
                    #pragma unroll
                    for (int ni = 0; ni < 4; ni++)
                        mma_f16(acc[mi][ni], a[mi], b[ni][0], b[ni][1]);
            }

            // this warp is done reading slot `buf` (ldsm results in regs)
            if (lane == 0) mbar_arrive(sbase + MB_CONS(buf));

            // producer: once all 8 warps consumed, refill the slot
            if (ch < 5 && tid == 0) {
                mbar_wait(sbase + MB_CONS(buf), cph[buf]);
                mbar_expect_tx(sbase + MB_FULL(buf), ACH_SZ);
                bulk_ldg(sbase + A_OFF + buf * ACH_SZ,
                         hin + (size_t)(ch + 3) * ACH_SZ,
                         ACH_SZ, sbase + MB_FULL(buf));
            }
            cph[buf] ^= 1;
            buf = (buf == 2) ? 0 : buf + 1;
        }
        __syncthreads();   // all warps done; gts (slot-0 alias) now safe

        // ---- K-split reduction: kw=1 warps publish partials ----
        float* gts = (float*)(sm + GT_OFF);
        if (kw == 1) {
            #pragma unroll
            for (int mi = 0; mi < 2; mi++)
                #pragma unroll
                for (int ni = 0; ni < 4; ni++) {
                    int row = mw * 32 + mi * 16 + (lane >> 2);
                    int col = ni * 8 + ((lane & 3) << 1);
                    gts[row * 33 + col]           = acc[mi][ni][0];
                    gts[row * 33 + col + 1]       = acc[mi][ni][1];
                    gts[(row + 8) * 33 + col]     = acc[mi][ni][2];
                    gts[(row + 8) * 33 + col + 1] = acc[mi][ni][3];
                }
        }
        __syncthreads();

        if (kw == 0) {
            // ---- LSTM update: 8 cells/thread, c in registers ----
            __half* houtT = g_h16T + (size_t)((t + 1) & 1) * (H_ * HTP);
            const __half* xps = (const __half*)(sm + XP_OFF + (t & 1) * XP_SZ);
            const int q2 = (lane & 3) << 1;
            #pragma unroll
            for (int mi = 0; mi < 2; mi++)
                #pragma unroll
                for (int ro = 0; ro < 2; ro++) {
                    int b = mw * 32 + mi * 16 + ro * 8 + (lane >> 2);
                    const float*  gb  = gts + b * 33;
                    const __half* xpb = xps + b * 40;
                    #pragma unroll
                    for (int j = 0; j < 2; j++) {
                        int hc = q2 + j;
                        int f  = ro * 2 + j;
                        float gi = acc[mi][0][f] + gb[hc]      + __half2float(xpb[hc]);
                        float gf = acc[mi][1][f] + gb[8 + hc]  + __half2float(xpb[8 + hc]);
                        float gg = acc[mi][2][f] + gb[16 + hc] + __half2float(xpb[16 + hc]);
                        float go = acc[mi][3][f] + gb[24 + hc] + __half2float(xpb[24 + hc]);
                        float it = sigmoidf_(gi);
                        float ft = sigmoidf_(gf);
                        float gt = tanhf(gg);
                        float ot = sigmoidf_(go);
                        int ci = mi * 4 + ro * 2 + j;
                        float c = ft * creg[ci] + it * gt;
                        creg[ci] = c;
                        float hv = ot * tanhf(c);
                        houtT[(col0 + hc) * HTP + b] = __float2half(hv);
                        if (t == T_ - 1) g_h[b * H_ + col0 + hc] = hv;
                    }
                }
        } else if (t < T_ - 1) {
            // ---- prefetch next step's xproj slice (overlaps LSTM math) ----
            prefetch_xp_half(sbase, t + 1, (t + 1) & 1, col0);
            cp_commit();
            cp_wait<0>();
        }

        // ---- grid barrier: per-CTA flags, parallel polling ----
        __syncthreads();
        if (tid == 0) {
            __threadfence();
            asm volatile("st.release.gpu.u32 [%0], %1;"
                         :: "l"(&g_flags[blockIdx.x * 64]), "r"((unsigned)(t + 1))
                         : "memory");
        }
        if (tid < NCTA) {
            unsigned v;
            do {
                asm volatile("ld.acquire.gpu.u32 %0, [%1];"
                             : "=r"(v) : "l"(&g_flags[tid * 64]));
            } while (v < (unsigned)(t + 1));
        }
        __syncthreads();
    }
}

// ---------------------------------------------------------------------------
// Logits GEMM (fp32): C[128,1024] = g_h @ Whp^T + bhp
// ---------------------------------------------------------------------------
__global__ __launch_bounds__(256)
void logits_gemm_kernel(const float* __restrict__ Bm,
                        const float* __restrict__ bias)
{
    __shared__ float As[16][65];
    __shared__ float Bs[16][65];

    const int bn = blockIdx.x;
    const int bm = blockIdx.y;
    const int tid = threadIdx.x;
    const int tx = tid & 15;
    const int ty = tid >> 4;

    const float* Ab = g_h + (size_t)bm * 64 * H_;
    const float* Bb = Bm  + (size_t)bn * 64 * H_;

    const int lrow = tid >> 2;
    const int lk   = (tid & 3) * 4;

    float acc[4][4];
    #pragma unroll
    for (int i = 0; i < 4; i++)
        #pragma unroll
        for (int j = 0; j < 4; j++) acc[i][j] = 0.f;

    for (int k0 = 0; k0 < H_; k0 += 16) {
        float4 av = *(const float4*)(Ab + (size_t)lrow * H_ + k0 + lk);
        float4 bv = *(const float4*)(Bb + (size_t)lrow * H_ + k0 + lk);
        As[lk + 0][lrow] = av.x; As[lk + 1][lrow] = av.y;
        As[lk + 2][lrow] = av.z; As[lk + 3][lrow] = av.w;
        Bs[lk + 0][lrow] = bv.x; Bs[lk + 1][lrow] = bv.y;
        Bs[lk + 2][lrow] = bv.z; Bs[lk + 3][lrow] = bv.w;
        __syncthreads();

        #pragma unroll
        for (int kk = 0; kk < 16; kk++) {
            float am[4], bnv[4];
            #pragma unroll
            for (int i = 0; i < 4; i++) am[i]  = As[kk][ty * 4 + i];
            #pragma unroll
            for (int j = 0; j < 4; j++) bnv[j] = Bs[kk][tx * 4 + j];
            #pragma unroll
            for (int i = 0; i < 4; i++)
                #pragma unroll
                for (int j = 0; j < 4; j++)
                    acc[i][j] = fmaf(am[i], bnv[j], acc[i][j]);
        }
        __syncthreads();
    }

    const int row0 = bm * 64 + ty * 4;
    const int col0 = bn * 64 + tx * 4;
    #pragma unroll
    for (int i = 0; i < 4; i++)
        #pragma unroll
        for (int j = 0; j < 4; j++)
            g_logits[(size_t)(row0 + i) * O_ + col0 + j] = acc[i][j] + bias[col0 + j];
}

// ---------------------------------------------------------------------------
// Softmax rows -> output
// ---------------------------------------------------------------------------
__global__ __launch_bounds__(256)
void softmax_kernel(float* __restrict__ out)
{
    __shared__ float red[256];
    const int b = blockIdx.x;
    const int tid = threadIdx.x;
    const float* lr = g_logits + (size_t)b * O_;

    float m = -INFINITY;
    for (int i = tid; i < O_; i += 256) m = fmaxf(m, lr[i]);
    red[tid] = m; __syncthreads();
    for (int s = 128; s > 0; s >>= 1) {
        if (tid < s) red[tid] = fmaxf(red[tid], red[tid + s]);
        __syncthreads();
    }
    m = red[0]; __syncthreads();

    float sum = 0.f;
    for (int i = tid; i < O_; i += 256) sum += expf(lr[i] - m);
    red[tid] = sum; __syncthreads();
    for (int s = 128; s > 0; s >>= 1) {
        if (tid < s) red[tid] += red[tid + s];
        __syncthreads();
    }
    float inv = 1.f / red[0];

    for (int i = tid; i < O_; i += 256)
        out[(size_t)b * O_ + i] = expf(lr[i] - m) * inv;
}

// ---------------------------------------------------------------------------
extern "C" void kernel_launch(void* const* d_in, const int* in_sizes, int n_in,
                              void* d_out, int out_size)
{
    const float* x   = (const float*)d_in[0];  // [B,T,D]
    const float* Wx  = (const float*)d_in[1];  // [4,H,D]
    const float* Wh  = (const float*)d_in[2];  // [4,H,H]
    const float* b   = (const float*)d_in[3];  // [4,H]
    const float* Whp = (const float*)d_in[4];  // [O,H]
    const float* bhp = (const float*)d_in[5];  // [O]
    float* out = (float*)d_out;

    __half *x16, *wx16, *wh16;
    cudaGetSymbolAddress((void**)&x16,  g_x16);
    cudaGetSymbolAddress((void**)&wx16, g_Wx16);
    cudaGetSymbolAddress((void**)&wh16, g_Wh16);

    // 1) conversions to fp16
    {
        int nx = B_ * T_ * D_;
        cvt16_kernel<<<(nx + 255) / 256, 256>>>(x, x16, nx);
        int nwx = G4H * D_;
        cvt16_kernel<<<(nwx + 255) / 256, 256>>>(Wx, wx16, nwx);
        int nwh = G4H * H_;
        cvt16_kernel<<<(nwh + 255) / 256, 256>>>(Wh, wh16, nwh);
    }

    // 2) xproj = x @ Wx^T + b  (fp16 output)
    {
        cudaFuncSetAttribute(xproj_kernel,
                             cudaFuncAttributeMaxDynamicSharedMemorySize,
                             SMEM_XPROJ);
        dim3 grid(G4H / 256, (B_ * T_) / 128);
        xproj_kernel<<<grid, 256, SMEM_XPROJ>>>(b);
    }

    // 3) init h + flags
    init_kernel<<<(2 * H_ * HTP + 255) / 256, 256>>>();

    // 4) persistent recurrence (all 256 steps in one launch)
    cudaFuncSetAttribute(lstm_persistent_kernel,
                         cudaFuncAttributeMaxDynamicSharedMemorySize, SMEM_LSTM);
    lstm_persistent_kernel<<<NCTA, 256, SMEM_LSTM>>>();

    // 5) logits + softmax
    {
        dim3 grid(O_ / 64, B_ / 64);
        logits_gemm_kernel<<<grid, 256>>>(Whp, bhp);
    }
    softmax_kernel<<<B_, 256>>>(out);
}

// round 12
// speedup vs baseline: 1.5336x; 1.0213x over previous
#include <cuda_runtime.h>
#include <cuda_fp16.h>
#include <math.h>
#include <stdint.h>

#define B_   128
#define T_   256
#define D_   512
#define H_   1024
#define O_   1024
#define G4H  4096
#define NCTA 128
#define HTP  136   // padded batch pitch (halfs) for transposed h; 272B rows

// ---------------- scratch (static device globals; no allocations) ----------
__device__ __align__(16) __half g_xproj[(size_t)B_ * T_ * G4H];  // fp16
__device__ float g_h[B_ * H_];
__device__ float g_logits[B_ * O_];
__device__ unsigned g_flags[NCTA * 64];            // per-CTA step flags, 256B stride

__device__ __align__(16) __half g_x16[(size_t)B_ * T_ * D_];
__device__ __align__(16) __half g_Wx16[G4H * D_];
__device__ __align__(16) __half g_Wh16[G4H * H_];
__device__ __align__(16) __half g_h16T[2 * H_ * HTP];   // ping-pong h, [k][b]

// ---------------------------------------------------------------------------
// helpers
// ---------------------------------------------------------------------------
__device__ __forceinline__ uint32_t smem_u32(const void* p) {
    return (uint32_t)__cvta_generic_to_shared(p);
}

__device__ __forceinline__ void ldsm4(uint32_t& r0, uint32_t& r1, uint32_t& r2,
                                      uint32_t& r3, uint32_t a) {
    asm volatile("ldmatrix.sync.aligned.m8n8.x4.shared.b16 {%0,%1,%2,%3}, [%4];"
                 : "=r"(r0), "=r"(r1), "=r"(r2), "=r"(r3) : "r"(a));
}

__device__ __forceinline__ void ldsm4t(uint32_t& r0, uint32_t& r1, uint32_t& r2,
                                       uint32_t& r3, uint32_t a) {
    asm volatile("ldmatrix.sync.aligned.m8n8.x4.trans.shared.b16 {%0,%1,%2,%3}, [%4];"
                 : "=r"(r0), "=r"(r1), "=r"(r2), "=r"(r3) : "r"(a));
}

__device__ __forceinline__ void mma_f16(float* c, const uint32_t* a,
                                        uint32_t b0, uint32_t b1) {
    asm volatile(
        "mma.sync.aligned.m16n8k16.row.col.f32.f16.f16.f32 "
        "{%0,%1,%2,%3}, {%4,%5,%6,%7}, {%8,%9}, {%0,%1,%2,%3};"
        : "+f"(c[0]), "+f"(c[1]), "+f"(c[2]), "+f"(c[3])
        : "r"(a[0]), "r"(a[1]), "r"(a[2]), "r"(a[3]), "r"(b0), "r"(b1));
}

__device__ __forceinline__ void cp_async16(uint32_t dst, const void* src) {
    asm volatile("cp.async.cg.shared.global [%0], [%1], 16;" :: "r"(dst), "l"(src));
}
__device__ __forceinline__ void cp_commit() {
    asm volatile("cp.async.commit_group;");
}
template <int N> __device__ __forceinline__ void cp_wait() {
    asm volatile("cp.async.wait_group %0;" :: "n"(N));
}

__device__ __forceinline__ void mbar_init(uint32_t mbar, uint32_t cnt) {
    asm volatile("mbarrier.init.shared::cta.b64 [%0], %1;" :: "r"(mbar), "r"(cnt));
}
__device__ __forceinline__ void mbar_expect_tx(uint32_t mbar, uint32_t bytes) {
    asm volatile("mbarrier.arrive.expect_tx.shared::cta.b64 _, [%0], %1;"
                 :: "r"(mbar), "r"(bytes));
}
__device__ __forceinline__ void mbar_arrive(uint32_t mbar) {
    asm volatile("mbarrier.arrive.release.cta.shared::cta.b64 _, [%0];"
                 :: "r"(mbar) : "memory");
}
__device__ __forceinline__ void bulk_ldg(uint32_t dst, const void* src,
                                         uint32_t bytes, uint32_t mbar) {
    asm volatile("cp.async.bulk.shared::cta.global.mbarrier::complete_tx::bytes "
                 "[%0], [%1], %2, [%3];"
                 :: "r"(dst), "l"(src), "r"(bytes), "r"(mbar) : "memory");
}
__device__ __forceinline__ void mbar_wait(uint32_t mbar, uint32_t phase) {
    asm volatile(
        "{\n\t.reg .pred p;\n\t"
        "WAIT_%=:\n\t"
        "mbarrier.try_wait.parity.acquire.cta.shared::cta.b64 p, [%0], %1;\n\t"
        "@!p bra WAIT_%=;\n\t}"
        :: "r"(mbar), "r"(phase) : "memory");
}

__device__ __forceinline__ float sigmoidf_(float x) {
    return 1.f / (1.f + __expf(-x));
}

// ---------------------------------------------------------------------------
// init + merged conversion kernels
// ---------------------------------------------------------------------------
__global__ void init_kernel()
{
    int i = blockIdx.x * blockDim.x + threadIdx.x;
    if (i < 2 * H_ * HTP) g_h16T[i] = __ushort_as_half((unsigned short)0);
    if (i < NCTA * 64) g_flags[i] = 0;
}

// single kernel converts x, Wx, Wh to fp16
__global__ void cvt_all_kernel(const float* __restrict__ x,
                               const float* __restrict__ Wx,
                               const float* __restrict__ Wh)
{
    const int NX  = B_ * T_ * D_;        // 16777216
    const int NWX = G4H * D_;            // 2097152
    const int NWH = G4H * H_;            // 4194304
    int i = blockIdx.x * blockDim.x + threadIdx.x;
    if (i < NX) {
        g_x16[i] = __float2half(x[i]);
    }
    if (i < NWX) g_Wx16[i] = __float2half(Wx[i]);
    if (i < NWH) g_Wh16[i] = __float2half(Wh[i]);
}

// ---------------------------------------------------------------------------
// xproj GEMM v3 (fp16 output): M=32768, N=4096, K=512.
// CTA tile M128 x N128, 256 threads = 8 warps (2M x 4N), warp tile m64 x n32.
// __launch_bounds__(256, 2) -> regs<=128 -> 2 CTAs/SM for latency hiding.
// ---------------------------------------------------------------------------
#define XA_SZ  (128 * 40 * 2)   // 10240 per buffer
#define XB_SZ  (128 * 40 * 2)   // 10240 per buffer
#define SMEM_XPROJ (2 * XA_SZ + 2 * XB_SZ)   // 40960

__global__ __launch_bounds__(256, 2)
void xproj_kernel(const float* __restrict__ bias)
{
    extern __shared__ char xsm[];
    const uint32_t sbase = smem_u32(xsm);
    const uint32_t Aoff = 0;
    const uint32_t Boff = 2 * XA_SZ;

    const int tid  = threadIdx.x;
    const int lane = tid & 31;
    const int w    = tid >> 5;
    const int mw   = w & 1;        // m64 group
    const int nw   = w >> 1;       // n32 group (0..3)
    const int m_off = blockIdx.y * 128;
    const int n0    = blockIdx.x * 128;

    float acc[4][4][4];
    #pragma unroll
    for (int mi = 0; mi < 4; mi++)
        #pragma unroll
        for (int ni = 0; ni < 4; ni++)
            #pragma unroll
            for (int r = 0; r < 4; r++) acc[mi][ni][r] = 0.f;

    // prologue: load chunk 0
    {
        #pragma unroll
        for (int ii = 0; ii < 2; ii++) {
            int u = tid + ii * 256;
            int row = u >> 2, q = u & 3;
            cp_async16(sbase + Aoff + row * 80 + q * 16,
                       g_x16 + (size_t)(m_off + row) * D_ + q * 8);
            cp_async16(sbase + Boff + row * 80 + q * 16,
                       g_Wx16 + (size_t)(n0 + row) * D_ + q * 8);
        }
        cp_commit();
    }

    int buf = 0;
    for (int ch = 0; ch < 16; ++ch) {
        if (ch < 15) {
            const int k0 = (ch + 1) * 32;
            const int nb = buf ^ 1;
            #pragma unroll
            for (int ii = 0; ii < 2; ii++) {
                int u = tid + ii * 256;
                int row = u >> 2, q = u & 3;
                cp_async16(sbase + Aoff + nb * XA_SZ + row * 80 + q * 16,
                           g_x16 + (size_t)(m_off + row) * D_ + k0 + q * 8);
                cp_async16(sbase + Boff + nb * XB_SZ + row * 80 + q * 16,
                           g_Wx16 + (size_t)(n0 + row) * D_ + k0 + q * 8);
            }
            cp_commit();
            cp_wait<1>();
        } else {
            cp_wait<0>();
        }
        __syncthreads();

        const uint32_t Ab = sbase + Aoff + buf * XA_SZ;
        const uint32_t Bb = sbase + Boff + buf * XB_SZ;
        #pragma unroll
        for (int kk = 0; kk < 32; kk += 16) {
            uint32_t a[4][4], b[4][2];
            int arow_l = (lane & 15);
            int acol = kk + ((lane >> 4) << 3);
            #pragma unroll
            for (int mi = 0; mi < 4; mi++) {
                int r = mw * 64 + mi * 16 + arow_l;
                ldsm4(a[mi][0], a[mi][1], a[mi][2], a[mi][3],
                      Ab + r * 80 + acol * 2);
            }
            int brow_l = ((lane >> 4) << 3) + (lane & 7);
            int bcol = kk + (((lane >> 3) & 1) << 3);
            #pragma unroll
            for (int nb2 = 0; nb2 < 2; nb2++) {
                int r = nw * 32 + nb2 * 16 + brow_l;
                ldsm4(b[nb2 * 2][0], b[nb2 * 2][1],
                      b[nb2 * 2 + 1][0], b[nb2 * 2 + 1][1],
                      Bb + r * 80 + bcol * 2);
            }
            #pragma unroll
            for (int mi = 0; mi < 4; mi++)
                #pragma unroll
                for (int ni = 0; ni < 4; ni++)
                    mma_f16(acc[mi][ni], a[mi], b[ni][0], b[ni][1]);
        }
        __syncthreads();
        buf ^= 1;
    }

    // epilogue: fp16 stores
    #pragma unroll
    for (int mi = 0; mi < 4; mi++) {
        #pragma unroll
        for (int ni = 0; ni < 4; ni++) {
            int grow = m_off + mw * 64 + mi * 16 + (lane >> 2);
            int gcol = n0 + nw * 32 + ni * 8 + ((lane & 3) << 1);
            float b0 = bias[gcol], b1 = bias[gcol + 1];
            *(__half2*)(g_xproj + (size_t)grow * G4H + gcol) =
                __floats2half2_rn(acc[mi][ni][0] + b0, acc[mi][ni][1] + b1);
            *(__half2*)(g_xproj + (size_t)(grow + 8) * G4H + gcol) =
                __floats2half2_rn(acc[mi][ni][2] + b0, acc[mi][ni][3] + b1);
        }
    }
}

// ---------------------------------------------------------------------------
// Persistent LSTM recurrence: 128 CTAs x 256 threads (unchanged from R11).
// ---------------------------------------------------------------------------
#define MB_FULL(i) ((i) * 8)
#define MB_CONS(i) (24 + (i) * 8)
#define WH_OFF     1024
#define WH_SZ      (32 * 2064)               // 66048
#define A_OFF      (WH_OFF + WH_SZ)          // 67072
#define ACH_SZ     (128 * 272)               // 34816 per ring slot
#define XP_OFF     (A_OFF + 3 * ACH_SZ)      // 171520
#define XP_SZ      (128 * 40 * 2)            // 10240 per buffer (fp16, 80B pitch)
#define GT_OFF     A_OFF                     // aliased with ring slot 0
#define SMEM_LSTM  (XP_OFF + 2 * XP_SZ)      // 192000

// prefetch next step's xproj slice (fp16); executed by threads 128..255
__device__ __forceinline__ void prefetch_xp_half(uint32_t sbase, int t, int buf,
                                                 int col0)
{
    const int tt = threadIdx.x - 128;        // 0..127
    #pragma unroll
    for (int ii = 0; ii < 4; ii++) {
        int u = tt + ii * 128;               // 0..511
        int b = u >> 2;
        int g = u & 3;
        cp_async16(sbase + XP_OFF + buf * XP_SZ + b * 80 + g * 16,
                   g_xproj + (((size_t)b * T_ + t) * 4 + g) * H_ + col0);
    }
}

__global__ __launch_bounds__(256, 1)
void lstm_persistent_kernel()
{
    extern __shared__ char sm[];
    const int tid  = threadIdx.x;
    const int lane = tid & 31;
    const int w    = tid >> 5;
    const int mw   = w & 3;       // m-tile 0..3
    const int kw   = w >> 2;      // k-half 0..1
    const int col0 = blockIdx.x * 8;
    const uint32_t sbase = smem_u32(sm);

    if (tid == 0) {
        #pragma unroll
        for (int i = 0; i < 3; i++) {
            mbar_init(sbase + MB_FULL(i), 1);
            mbar_init(sbase + MB_CONS(i), 8);   // one arrive per warp
        }
    }
    __syncthreads();

    // ---- resident Wh load (fp16), gate-major rows ----
    for (int i = tid; i < 4096; i += 256) {       // 16B units
        int r = i >> 7;
        int c = i & 127;
        int ng = (r >> 3) * H_ + col0 + (r & 7);
        cp_async16(sbase + WH_OFF + r * 2064 + c * 16,
                   g_Wh16 + (size_t)ng * H_ + c * 8);
    }
    if (tid >= 128) prefetch_xp_half(sbase, 0, 0, col0);
    cp_commit();
    cp_wait<0>();
    __syncthreads();

    uint32_t fph[3] = {0, 0, 0};
    uint32_t cph[3] = {0, 0, 0};
    float creg[8];
    #pragma unroll
    for (int i = 0; i < 8; i++) creg[i] = 0.f;

    for (int t = 0; t < T_; ++t) {
        const char* hin = (const char*)(g_h16T + (size_t)(t & 1) * (H_ * HTP));

        // prologue: fill the 3-deep ring (slots free: end-of-step sync+barrier)
        if (tid == 0) {
            #pragma unroll
            for (int c = 0; c < 3; c++) {
                mbar_expect_tx(sbase + MB_FULL(c), ACH_SZ);
                bulk_ldg(sbase + A_OFF + c * ACH_SZ, hin + c * ACH_SZ,
                         ACH_SZ, sbase + MB_FULL(c));
            }
        }

        float acc[2][4][4];
        #pragma unroll
        for (int mi = 0; mi < 2; mi++)
            #pragma unroll
            for (int ni = 0; ni < 4; ni++)
                #pragma unroll
                for (int r = 0; r < 4; r++) acc[mi][ni][r] = 0.f;

        int buf = 0;
        for (int ch = 0; ch < 8; ++ch) {
            mbar_wait(sbase + MB_FULL(buf), fph[buf]);
            fph[buf] ^= 1;

            const uint32_t Abuf = sbase + A_OFF + buf * ACH_SZ;
            #pragma unroll
            for (int kk = 0; kk < 64; kk += 16) {
                const int kloc = kw * 64 + kk;           // k within chunk
                uint32_t a[2][4];
                int krow = kloc + ((lane >> 4) << 3) + (lane & 7);
                #pragma unroll
                for (int mi = 0; mi < 2; mi++) {
                    int mcol = mw * 32 + mi * 16 + (((lane >> 3) & 1) << 3);
                    ldsm4t(a[mi][0], a[mi][1], a[mi][2], a[mi][3],
                           Abuf + krow * 272 + mcol * 2);
                }
                uint32_t b[4][2];
                const int kglob = ch * 128 + kloc;
                #pragma unroll
                for (int nh = 0; nh < 2; nh++) {
                    int brow = nh * 16 + ((lane >> 4) << 3) + (lane & 7);
                    int bcol = (kglob + (((lane >> 3) & 1) << 3)) * 2;
                    ldsm4(b[nh * 2][0], b[nh * 2][1],
                          b[nh * 2 + 1][0], b[nh * 2 + 1][1],
                          sbase + WH_OFF + brow * 2064 + bcol);
                }
                #pragma unroll
                for (int mi = 0; mi < 2; mi++)
                    #pragma unroll
                    for (int ni = 0; ni < 4; ni++)
                        mma_f16(acc[mi][ni], a[mi], b[ni][0], b[ni][1]);
            }

            // this warp is done reading slot `buf` (ldsm results in regs)
            if (lane == 0) mbar_arrive(sbase + MB_CONS(buf));

            // producer: once all 8 warps consumed, refill the slot
            if (ch < 5 && tid == 0) {
                mbar_wait(sbase + MB_CONS(buf), cph[buf]);
                mbar_expect_tx(sbase + MB_FULL(buf), ACH_SZ);
                bulk_ldg(sbase + A_OFF + buf * ACH_SZ,
                         hin + (size_t)(ch + 3) * ACH_SZ,
                         ACH_SZ, sbase + MB_FULL(buf));
            }
            cph[buf] ^= 1;
            buf = (buf == 2) ? 0 : buf + 1;
        }
        __syncthreads();   // all warps done; gts (slot-0 alias) now safe

        // ---- K-split reduction: kw=1 warps publish partials ----
        float* gts = (float*)(sm + GT_OFF);
        if (kw == 1) {
            #pragma unroll
            for (int mi = 0; mi < 2; mi++)
                #pragma unroll
                for (int ni = 0; ni < 4; ni++) {
                    int row = mw * 32 + mi * 16 + (lane >> 2);
                    int col = ni * 8 + ((lane & 3) << 1);
                    gts[row * 33 + col]           = acc[mi][ni][0];
                    gts[row * 33 + col + 1]       = acc[mi][ni][1];
                    gts[(row + 8) * 33 + col]     = acc[mi][ni][2];
                    gts[(row + 8) * 33 + col + 1] = acc[mi][ni][3];
                }
        }
        __syncthreads();

        if (kw == 0) {
            // ---- LSTM update: 8 cells/thread, c in registers ----
            __half* houtT = g_h16T + (size_t)((t + 1) & 1) * (H_ * HTP);
            const __half* xps = (const __half*)(sm + XP_OFF + (t & 1) * XP_SZ);
            const int q2 = (lane & 3) << 1;
            #pragma unroll
            for (int mi = 0; mi < 2; mi++)
                #pragma unroll
                for (int ro = 0; ro < 2; ro++) {
                    int b = mw * 32 + mi * 16 + ro * 8 + (lane >> 2);
                    const float*  gb  = gts + b * 33;
                    const __half* xpb = xps + b * 40;
                    #pragma unroll
                    for (int j = 0; j < 2; j++) {
                        int hc = q2 + j;
                        int f  = ro * 2 + j;
                        float gi = acc[mi][0][f] + gb[hc]      + __half2float(xpb[hc]);
                        float gf = acc[mi][1][f] + gb[8 + hc]  + __half2float(xpb[8 + hc]);
                        float gg = acc[mi][2][f] + gb[16 + hc] + __half2float(xpb[16 + hc]);
                        float go = acc[mi][3][f] + gb[24 + hc] + __half2float(xpb[24 + hc]);
                        float it = sigmoidf_(gi);
                        float ft = sigmoidf_(gf);
                        float gt = tanhf(gg);
                        float ot = sigmoidf_(go);
                        int ci = mi * 4 + ro * 2 + j;
                        float c = ft * creg[ci] + it * gt;
                        creg[ci] = c;
                        float hv = ot * tanhf(c);
                        houtT[(col0 + hc) * HTP + b] = __float2half(hv);
                        if (t == T_ - 1) g_h[b * H_ + col0 + hc] = hv;
                    }
                }
        } else if (t < T_ - 1) {
            // ---- prefetch next step's xproj slice (overlaps LSTM math) ----
            prefetch_xp_half(sbase, t + 1, (t + 1) & 1, col0);
            cp_commit();
            cp_wait<0>();
        }

        // ---- grid barrier: per-CTA flags, parallel polling ----
        __syncthreads();
        if (tid == 0) {
            __threadfence();
            asm volatile("st.release.gpu.u32 [%0], %1;"
                         :: "l"(&g_flags[blockIdx.x * 64]), "r"((unsigned)(t + 1))
                         : "memory");
        }
        if (tid < NCTA) {
            unsigned v;
            do {
                asm volatile("ld.acquire.gpu.u32 %0, [%1];"
                             : "=r"(v) : "l"(&g_flags[tid * 64]));
            } while (v < (unsigned)(t + 1));
        }
        __syncthreads();
    }
}

// ---------------------------------------------------------------------------
// Logits GEMM (fp32): C[128,1024] = g_h @ Whp^T + bhp
// ---------------------------------------------------------------------------
__global__ __launch_bounds__(256)
void logits_gemm_kernel(const float* __restrict__ Bm,
                        const float* __restrict__ bias)
{
    __shared__ float As[16][65];
    __shared__ float Bs[16][65];

    const int bn = blockIdx.x;
    const int bm = blockIdx.y;
    const int tid = threadIdx.x;
    const int tx = tid & 15;
    const int ty = tid >> 4;

    const float* Ab = g_h + (size_t)bm * 64 * H_;
    const float* Bb = Bm  + (size_t)bn * 64 * H_;

    const int lrow = tid >> 2;
    const int lk   = (tid & 3) * 4;

    float acc[4][4];
    #pragma unroll
    for (int i = 0; i < 4; i++)
        #pragma unroll
        for (int j = 0; j < 4; j++) acc[i][j] = 0.f;

    for (int k0 = 0; k0 < H_; k0 += 16) {
        float4 av = *(const float4*)(Ab + (size_t)lrow * H_ + k0 + lk);
        float4 bv = *(const float4*)(Bb + (size_t)lrow * H_ + k0 + lk);
        As[lk + 0][lrow] = av.x; As[lk + 1][lrow] = av.y;
        As[lk + 2][lrow] = av.z; As[lk + 3][lrow] = av.w;
        Bs[lk + 0][lrow] = bv.x; Bs[lk + 1][lrow] = bv.y;
        Bs[lk + 2][lrow] = bv.z; Bs[lk + 3][lrow] = bv.w;
        __syncthreads();

        #pragma unroll
        for (int kk = 0; kk < 16; kk++) {
            float am[4], bnv[4];
            #pragma unroll
            for (int i = 0; i < 4; i++) am[i]  = As[kk][ty * 4 + i];
            #pragma unroll
            for (int j = 0; j < 4; j++) bnv[j] = Bs[kk][tx * 4 + j];
            #pragma unroll
            for (int i = 0; i < 4; i++)
                #pragma unroll
                for (int j = 0; j < 4; j++)
                    acc[i][j] = fmaf(am[i], bnv[j], acc[i][j]);
        }
        __syncthreads();
    }

    const int row0 = bm * 64 + ty * 4;
    const int col0 = bn * 64 + tx * 4;
    #pragma unroll
    for (int i = 0; i < 4; i++)
        #pragma unroll
        for (int j = 0; j < 4; j++)
            g_logits[(size_t)(row0 + i) * O_ + col0 + j] = acc[i][j] + bias[col0 + j];
}

// ---------------------------------------------------------------------------
// Softmax rows -> output
// ---------------------------------------------------------------------------
__global__ __launch_bounds__(256)
void softmax_kernel(float* __restrict__ out)
{
    __shared__ float red[256];
    const int b = blockIdx.x;
    const int tid = threadIdx.x;
    const float* lr = g_logits + (size_t)b * O_;

    float m = -INFINITY;
    for (int i = tid; i < O_; i += 256) m = fmaxf(m, lr[i]);
    red[tid] = m; __syncthreads();
    for (int s = 128; s > 0; s >>= 1) {
        if (tid < s) red[tid] = fmaxf(red[tid], red[tid + s]);
        __syncthreads();
    }
    m = red[0]; __syncthreads();

    float sum = 0.f;
    for (int i = tid; i < O_; i += 256) sum += expf(lr[i] - m);
    red[tid] = sum; __syncthreads();
    for (int s = 128; s > 0; s >>= 1) {
        if (tid < s) red[tid] += red[tid + s];
        __syncthreads();
    }
    float inv = 1.f / red[0];

    for (int i = tid; i < O_; i += 256)
        out[(size_t)b * O_ + i] = expf(lr[i] - m) * inv;
}

// ---------------------------------------------------------------------------
extern "C" void kernel_launch(void* const* d_in, const int* in_sizes, int n_in,
                              void* d_out, int out_size)
{
    const float* x   = (const float*)d_in[0];  // [B,T,D]
    const float* Wx  = (const float*)d_in[1];  // [4,H,D]
    const float* Wh  = (const float*)d_in[2];  // [4,H,H]
    const float* b   = (const float*)d_in[3];  // [4,H]
    const float* Whp = (const float*)d_in[4];  // [O,H]
    const float* bhp = (const float*)d_in[5];  // [O]
    float* out = (float*)d_out;

    // 1) init h + flags (independent; first for ncu slot alignment)
    init_kernel<<<(2 * H_ * HTP + 255) / 256, 256>>>();

    // 2) merged conversions to fp16
    {
        int n = B_ * T_ * D_;   // largest of the three
        cvt_all_kernel<<<(n + 255) / 256, 256>>>(x, Wx, Wh);
    }

    // 3) xproj = x @ Wx^T + b  (v3: M128N128, 2 CTAs/SM)
    {
        cudaFuncSetAttribute(xproj_kernel,
                             cudaFuncAttributeMaxDynamicSharedMemorySize,
                             SMEM_XPROJ);
        dim3 grid(G4H / 128, (B_ * T_) / 128);
        xproj_kernel<<<grid, 256, SMEM_XPROJ>>>(b);
    }

    // 4) persistent recurrence (all 256 steps in one launch)
    cudaFuncSetAttribute(lstm_persistent_kernel,
                         cudaFuncAttributeMaxDynamicSharedMemorySize, SMEM_LSTM);
    lstm_persistent_kernel<<<NCTA, 256, SMEM_LSTM>>>();

    // 5) logits + softmax
    {
        dim3 grid(O_ / 64, B_ / 64);
        logits_gemm_kernel<<<grid, 256>>>(Whp, bhp);
    }
    softmax_kernel<<<B_, 256>>>(out);
}